// round 8
// baseline (speedup 1.0000x reference)
#include <cuda_runtime.h>
#include <cstdint>

#define BB   128
#define DD   1024
#define HH1  512
#define HH2  256

typedef unsigned int u32;

// ---------------- scratch (device globals; no allocation allowed) ----------
__device__ float g_c1[BB * HH1];
__device__ float g_s1[BB * HH1];
__device__ float g_c2[BB * HH2];
__device__ float g_s2[BB * HH2];
__device__ float g_c3[BB * HH1];
__device__ float g_s3[BB * HH1];
__device__ float g_W1T[DD * HH1];                 // W1^T fp32 [1024,512]
__device__ char  g_qW1a[DD * HH1];                // W1^T digit1
__device__ char  g_qW1b[DD * HH1];                // W1^T digit2
__device__ float g_sW1[DD];
__device__ char  g_qB3a[BB * HH2 * HH1];          // (W2*s3) digits [b][e][h]
__device__ char  g_qB3b[BB * HH2 * HH1];
__device__ char  g_qB1a[BB * HH2 * HH1];          // (W2*s1) digits
__device__ char  g_qB1b[BB * HH2 * HH1];
__device__ float g_sB3[BB * HH2];
__device__ float g_sB1[BB * HH2];                 // has s2 folded in
__device__ float g_Mf[(size_t)BB * DD * HH2];     // M1 fp32 [b][1024,256]
__device__ float g_Lf[(size_t)BB * DD * HH2];     // L  fp32
__device__ char  g_qMa[(size_t)BB * DD * HH2];
__device__ char  g_qMb[(size_t)BB * DD * HH2];
__device__ char  g_qLa[(size_t)BB * DD * HH2];
__device__ char  g_qLb[(size_t)BB * DD * HH2];
__device__ float g_sM[BB * DD];
__device__ float g_sL[BB * DD];

// ---------------- helpers ----------------------------------------------------
__device__ __forceinline__ u32 smem_u32(const void* p) {
    u32 a;
    asm("{ .reg .u64 t; cvta.to.shared.u64 t, %1; cvt.u32.u64 %0, t; }"
        : "=r"(a) : "l"(p));
    return a;
}

__device__ __forceinline__ void cpa16(u32 dst, const void* src) {
    asm volatile("cp.async.cg.shared.global [%0], [%1], 16;"
                 :: "r"(dst), "l"(src) : "memory");
}
#define CP_COMMIT() asm volatile("cp.async.commit_group;" ::: "memory")
#define CP_WAIT0()  asm volatile("cp.async.wait_group 0;" ::: "memory")

__device__ __forceinline__ void ldsm4(u32* r, u32 addr) {
    asm volatile("ldmatrix.sync.aligned.m8n8.x4.shared.b16 {%0,%1,%2,%3}, [%4];"
                 : "=r"(r[0]), "=r"(r[1]), "=r"(r[2]), "=r"(r[3]) : "r"(addr));
}

__device__ __forceinline__ void mma_s8(int* c, const u32* a, const u32* b) {
    asm volatile("mma.sync.aligned.m16n8k32.row.col.s32.s8.s8.s32 "
                 "{%0,%1,%2,%3}, {%4,%5,%6,%7}, {%8,%9}, {%0,%1,%2,%3};"
                 : "+r"(c[0]), "+r"(c[1]), "+r"(c[2]), "+r"(c[3])
                 : "r"(a[0]), "r"(a[1]), "r"(a[2]), "r"(a[3]),
                   "r"(b[0]), "r"(b[1]));
}

__device__ __forceinline__ u32 pack4(int a, int b, int c, int d) {
    return (u32)(a & 0xFF) | (((u32)(b & 0xFF)) << 8)
         | (((u32)(c & 0xFF)) << 16) | (((u32)(d & 0xFF)) << 24);
}

// ---------------- forward pass -----------------------------------------------
__global__ void fwd_kernel(const float* __restrict__ A,
                           const float* __restrict__ W,
                           const float* __restrict__ bias,
                           float* __restrict__ c_out,
                           float* __restrict__ s_out,
                           float* __restrict__ extra_out,
                           int K, int N, int transW) {
    __shared__ float sA[4][1024];
    const int b0  = blockIdx.y * 4;
    const int tid = threadIdx.x;
    #pragma unroll
    for (int bi = 0; bi < 4; ++bi) {
        const float4* src = (const float4*)(A + (size_t)(b0 + bi) * K);
        float4* dst = (float4*)sA[bi];
        for (int k = tid; k < (K >> 2); k += 128) dst[k] = src[k];
    }
    __syncthreads();
    const int on = tid >> 2, kq = tid & 3;
    const int n  = blockIdx.x * 32 + on;
    const int kpt = K >> 2;
    const int k0  = kq * kpt;
    float acc[4] = {0.f, 0.f, 0.f, 0.f};
    if (transW) {
        const float* wr = W + (size_t)n * K + k0;
        #pragma unroll 2
        for (int k = 0; k < kpt; k += 4) {
            float4 w4 = *(const float4*)(wr + k);
            #pragma unroll
            for (int bi = 0; bi < 4; ++bi) {
                float4 x4 = *(const float4*)(&sA[bi][k0 + k]);
                acc[bi] += x4.x * w4.x + x4.y * w4.y + x4.z * w4.z + x4.w * w4.w;
            }
        }
    } else {
        #pragma unroll 2
        for (int k = 0; k < kpt; k += 4) {
            float w0 = W[(size_t)(k0 + k) * N + n];
            float w1 = W[(size_t)(k0 + k + 1) * N + n];
            float w2 = W[(size_t)(k0 + k + 2) * N + n];
            float w3 = W[(size_t)(k0 + k + 3) * N + n];
            #pragma unroll
            for (int bi = 0; bi < 4; ++bi) {
                acc[bi] += sA[bi][k0 + k] * w0 + sA[bi][k0 + k + 1] * w1
                         + sA[bi][k0 + k + 2] * w2 + sA[bi][k0 + k + 3] * w3;
            }
        }
    }
    #pragma unroll
    for (int bi = 0; bi < 4; ++bi) {
        acc[bi] += __shfl_xor_sync(0xFFFFFFFFu, acc[bi], 1);
        acc[bi] += __shfl_xor_sync(0xFFFFFFFFu, acc[bi], 2);
    }
    if (kq == 0) {
        const float bv = bias[n];
        #pragma unroll
        for (int bi = 0; bi < 4; ++bi) {
            const float c = 1.0f / (1.0f + expf(-(acc[bi] + bv)));
            const size_t o = (size_t)(b0 + bi) * N + n;
            if (c_out)     c_out[o]     = c;
            if (s_out)     s_out[o]     = c * (1.0f - c);
            if (extra_out) extra_out[o] = c;
        }
    }
}

// ---------------- one-time transpose of W1 to fp32 ---------------------------
__global__ void transpose_f32_k(const float* __restrict__ in, int R, int C,
                                float* __restrict__ out) {
    __shared__ float t[32][33];
    const int c0 = blockIdx.x * 32, r0 = blockIdx.y * 32;
    const int tx = threadIdx.x, ty = threadIdx.y;
    #pragma unroll
    for (int i = 0; i < 32; i += 8)
        t[ty + i][tx] = in[(size_t)(r0 + ty + i) * C + c0 + tx];
    __syncthreads();
    #pragma unroll
    for (int i = 0; i < 32; i += 8)
        out[(size_t)(c0 + ty + i) * R + r0 + tx] = t[tx][ty + i];
}

// ---------------- row quantizers ---------------------------------------------
// One warp per row of C = 32*CPL fp32 values -> 2 int8 digits + scale.
template <int CPL>
__global__ void quant_rows(const float* __restrict__ X,
                           char* __restrict__ q1, char* __restrict__ q2,
                           float* __restrict__ sOut) {
    const int warp = (blockIdx.x * blockDim.x + threadIdx.x) >> 5;
    const int lane = threadIdx.x & 31;
    const int C = 32 * CPL;
    const float* xr = X + (size_t)warp * C + lane * CPL;
    float v[CPL];
    #pragma unroll
    for (int i = 0; i < CPL; i += 4) {
        float4 t = *(const float4*)(xr + i);
        v[i] = t.x; v[i+1] = t.y; v[i+2] = t.z; v[i+3] = t.w;
    }
    float m = 0.f;
    #pragma unroll
    for (int i = 0; i < CPL; ++i) m = fmaxf(m, fabsf(v[i]));
    #pragma unroll
    for (int o = 16; o; o >>= 1) m = fmaxf(m, __shfl_xor_sync(0xFFFFFFFFu, m, o));
    const float s   = m * (1.0f / 127.0f);
    const float inv = (m > 0.f) ? (127.0f / m) : 0.f;
    u32 w1[CPL / 4], w2[CPL / 4];
    #pragma unroll
    for (int i = 0; i < CPL; i += 4) {
        int a0 = __float2int_rn(v[i] * inv);
        int a1 = __float2int_rn(v[i+1] * inv);
        int a2 = __float2int_rn(v[i+2] * inv);
        int a3 = __float2int_rn(v[i+3] * inv);
        int b0 = __float2int_rn((v[i]   - a0 * s) * inv * 128.f);
        int b1 = __float2int_rn((v[i+1] - a1 * s) * inv * 128.f);
        int b2 = __float2int_rn((v[i+2] - a2 * s) * inv * 128.f);
        int b3 = __float2int_rn((v[i+3] - a3 * s) * inv * 128.f);
        w1[i / 4] = pack4(a0, a1, a2, a3);
        w2[i / 4] = pack4(b0, b1, b2, b3);
    }
    u32* d1 = (u32*)(q1 + (size_t)warp * C + lane * CPL);
    u32* d2 = (u32*)(q2 + (size_t)warp * C + lane * CPL);
    #pragma unroll
    for (int i = 0; i < CPL / 4; ++i) { d1[i] = w1[i]; d2[i] = w2[i]; }
    if (lane == 0) sOut[warp] = s;
}

// Quantize rows of B[b][e,h] = W2[e,h]*sv[b,h]; stored scale optionally *fold[row].
__global__ void quant_B(const float* __restrict__ W2, const float* __restrict__ sv,
                        const float* __restrict__ fold,
                        char* __restrict__ q1, char* __restrict__ q2,
                        float* __restrict__ sOut) {
    const int row  = (blockIdx.x * blockDim.x + threadIdx.x) >> 5;  // b*256 + e
    const int lane = threadIdx.x & 31;
    const int bb = row >> 8, e = row & 255;
    const float* wr = W2 + (size_t)e * HH1 + lane * 16;
    const float* sr = sv + (size_t)bb * HH1 + lane * 16;
    float v[16];
    #pragma unroll
    for (int i = 0; i < 16; i += 4) {
        float4 w = *(const float4*)(wr + i);
        float4 s4 = *(const float4*)(sr + i);
        v[i] = w.x * s4.x; v[i+1] = w.y * s4.y; v[i+2] = w.z * s4.z; v[i+3] = w.w * s4.w;
    }
    float m = 0.f;
    #pragma unroll
    for (int i = 0; i < 16; ++i) m = fmaxf(m, fabsf(v[i]));
    #pragma unroll
    for (int o = 16; o; o >>= 1) m = fmaxf(m, __shfl_xor_sync(0xFFFFFFFFu, m, o));
    const float s   = m * (1.0f / 127.0f);
    const float inv = (m > 0.f) ? (127.0f / m) : 0.f;
    u32 w1[4], w2b[4];
    #pragma unroll
    for (int i = 0; i < 16; i += 4) {
        int a0 = __float2int_rn(v[i] * inv);
        int a1 = __float2int_rn(v[i+1] * inv);
        int a2 = __float2int_rn(v[i+2] * inv);
        int a3 = __float2int_rn(v[i+3] * inv);
        int b0 = __float2int_rn((v[i]   - a0 * s) * inv * 128.f);
        int b1 = __float2int_rn((v[i+1] - a1 * s) * inv * 128.f);
        int b2 = __float2int_rn((v[i+2] - a2 * s) * inv * 128.f);
        int b3 = __float2int_rn((v[i+3] - a3 * s) * inv * 128.f);
        w1[i / 4]  = pack4(a0, a1, a2, a3);
        w2b[i / 4] = pack4(b0, b1, b2, b3);
    }
    u32* d1 = (u32*)(q1 + (size_t)row * HH1 + lane * 16);
    u32* d2 = (u32*)(q2 + (size_t)row * HH1 + lane * 16);
    #pragma unroll
    for (int i = 0; i < 4; ++i) { d1[i] = w1[i]; d2[i] = w2b[i]; }
    if (lane == 0) sOut[row] = fold ? s * fold[row] : s;
}

// ---------------- int8 2-digit batched GEMM ----------------------------------
// C[b][m,n] = sA[b?,m]*sB[b,n]*( P + Q/128 ),  P = sum a1b1, Q = sum a1b2+a2b1
// CTA 128x128, 8 warps (warp 64x32), BK=64 bytes, cp.async double-buffered.
#define ROWP  80
#define MATB  (128 * ROWP)                  // 10240
#define STAGE_BYTES (4 * MATB)              // 40960
#define SMEM_GEMM_BYTES (2 * STAGE_BYTES)   // 81920

__global__ void __launch_bounds__(256, 1)
gemm_i8(const char* __restrict__ qA1, const char* __restrict__ qA2, size_t strideA,
        const char* __restrict__ qB1, const char* __restrict__ qB2, size_t strideB,
        const float* __restrict__ sA, size_t strideSA,
        const float* __restrict__ sB, int Nn, int K,
        float* __restrict__ Cf, size_t ldc, size_t strideC) {
    extern __shared__ char smem[];
    const u32 sb  = smem_u32(smem);
    const int tid = threadIdx.x;
    const int wid = tid >> 5;
    const int lid = tid & 31;
    const int b   = blockIdx.z;
    const int n0  = blockIdx.x * 128;
    const int m0  = blockIdx.y * 128;

    const int m0w = (wid & 1) * 64;          // 2 warps in M
    const int n0w = (wid >> 1) * 32;         // 4 warps in N

    // ---- loader: 256 threads, one row each (A side / B side) ----
    const int side = tid >> 7;
    const int r    = tid & 127;
    const char* src1 = side ? (qB1 + (size_t)b * strideB + (size_t)(n0 + r) * K)
                            : (qA1 + (size_t)b * strideA + (size_t)(m0 + r) * K);
    const char* src2 = side ? (qB2 + (size_t)b * strideB + (size_t)(n0 + r) * K)
                            : (qA2 + (size_t)b * strideA + (size_t)(m0 + r) * K);
    const u32 so = (side ? 2 * MATB : 0) + (u32)r * ROWP;

    // ---- ldmatrix lane address bases (byte-identical to verified bf16 maps) --
    const int l = lid;
    const u32 a_base = (u32)((m0w + (l & 7) + ((l >> 3) & 1) * 8) * ROWP
                             + ((l >> 4) & 1) * 16);
    const int mt = l >> 3;
    const u32 b_base = (u32)((n0w + ((mt >> 1) & 1) * 8 + (l & 7)) * ROWP
                             + (mt & 1) * 16);

    int accP[4][4][4], accQ[4][4][4];
    #pragma unroll
    for (int i = 0; i < 4; i++)
        #pragma unroll
        for (int j = 0; j < 4; j++)
            #pragma unroll
            for (int q = 0; q < 4; q++) { accP[i][j][q] = 0; accQ[i][j][q] = 0; }

    auto issue_stage = [&](int sidx, int kt) {
        const u32 stg = sb + (u32)sidx * STAGE_BYTES + so;
        #pragma unroll
        for (int j = 0; j < 4; ++j) cpa16(stg + j * 16, src1 + kt + j * 16);
        #pragma unroll
        for (int j = 0; j < 4; ++j) cpa16(stg + MATB + j * 16, src2 + kt + j * 16);
        CP_COMMIT();
    };

    const int niter = K >> 6;
    issue_stage(0, 0);

    for (int it = 0; it < niter; ++it) {
        const u32 stg = sb + (u32)(it & 1) * STAGE_BYTES;
        CP_WAIT0();
        __syncthreads();
        if (it + 1 < niter) issue_stage((it + 1) & 1, (it + 1) << 6);

        const u32 aQ1 = stg + a_base;
        const u32 aQ2 = stg + MATB + a_base;
        const u32 bQ1 = stg + 2 * MATB + b_base;
        const u32 bQ2 = stg + 3 * MATB + b_base;

        #pragma unroll
        for (int ks = 0; ks < 2; ++ks) {
            u32 A1f[4][4], A2f[4][4], B1f[2][4], B2f[2][4];
            #pragma unroll
            for (int mi = 0; mi < 4; ++mi) {
                ldsm4(A1f[mi], aQ1 + mi * (16 * ROWP) + ks * 32);
                ldsm4(A2f[mi], aQ2 + mi * (16 * ROWP) + ks * 32);
            }
            #pragma unroll
            for (int g = 0; g < 2; ++g) {
                ldsm4(B1f[g], bQ1 + g * (16 * ROWP) + ks * 32);
                ldsm4(B2f[g], bQ2 + g * (16 * ROWP) + ks * 32);
            }
            #pragma unroll
            for (int g = 0; g < 2; ++g)
                #pragma unroll
                for (int h = 0; h < 2; ++h) {
                    const int nj = 2 * g + h;
                    #pragma unroll
                    for (int mi = 0; mi < 4; ++mi) {
                        mma_s8(accP[mi][nj], A1f[mi], &B1f[g][2 * h]);
                        mma_s8(accQ[mi][nj], A1f[mi], &B2f[g][2 * h]);
                        mma_s8(accQ[mi][nj], A2f[mi], &B1f[g][2 * h]);
                    }
                }
        }
        __syncthreads();
    }

    // ---- epilogue: C = sA[row]*sB[col]*(P + Q/128) ----
    const int gid = lid >> 2;
    const int tig = lid & 3;
    const float* sAb = sA + (size_t)b * strideSA;
    const float* sBb = sB + (size_t)b * Nn;
    #pragma unroll
    for (int mi = 0; mi < 4; ++mi) {
        const int row = m0 + m0w + 16 * mi + gid;
        const float ra = sAb[row];
        const float rb = sAb[row + 8];
        #pragma unroll
        for (int nj = 0; nj < 4; ++nj) {
            const int col = n0 + n0w + 8 * nj + 2 * tig;
            const float cs0 = sBb[col];
            const float cs1 = sBb[col + 1];
            float p0 = (float)accP[mi][nj][0] + 0.0078125f * (float)accQ[mi][nj][0];
            float p1 = (float)accP[mi][nj][1] + 0.0078125f * (float)accQ[mi][nj][1];
            float p2 = (float)accP[mi][nj][2] + 0.0078125f * (float)accQ[mi][nj][2];
            float p3 = (float)accP[mi][nj][3] + 0.0078125f * (float)accQ[mi][nj][3];
            const size_t o0 = (size_t)b * strideC + (size_t)row * ldc + col;
            const size_t o1 = o0 + 8 * ldc;
            *(float2*)(Cf + o0) = make_float2(p0 * ra * cs0, p1 * ra * cs1);
            *(float2*)(Cf + o1) = make_float2(p2 * rb * cs0, p3 * rb * cs1);
        }
    }
}

// ---------------- launcher ---------------------------------------------------
extern "C" void kernel_launch(void* const* d_in, const int* in_sizes, int n_in,
                              void* d_out, int out_size) {
    const float* x   = (const float*)d_in[0];
    const float* W1  = (const float*)d_in[1];
    const float* b1  = (const float*)d_in[2];
    const float* W2  = (const float*)d_in[3];
    const float* b2  = (const float*)d_in[4];
    const float* b3  = (const float*)d_in[5];
    const float* b_r = (const float*)d_in[6];

    float* out     = (float*)d_out;
    float* out_rec = out;                           // [128,1024]
    float* out_c2  = out + (size_t)BB * DD;         // [128,256]
    float* out_jac = out_c2 + (size_t)BB * HH2;     // [D, B, D] flat

    float *c1, *s1, *c2, *s2, *c3, *s3, *W1T, *sW1, *sB3, *sB1, *Mf, *Lf, *sM, *sL;
    char *qW1a, *qW1b, *qB3a, *qB3b, *qB1a, *qB1b, *qMa, *qMb, *qLa, *qLb;
    cudaGetSymbolAddress((void**)&c1, g_c1);
    cudaGetSymbolAddress((void**)&s1, g_s1);
    cudaGetSymbolAddress((void**)&c2, g_c2);
    cudaGetSymbolAddress((void**)&s2, g_s2);
    cudaGetSymbolAddress((void**)&c3, g_c3);
    cudaGetSymbolAddress((void**)&s3, g_s3);
    cudaGetSymbolAddress((void**)&W1T, g_W1T);
    cudaGetSymbolAddress((void**)&sW1, g_sW1);
    cudaGetSymbolAddress((void**)&sB3, g_sB3);
    cudaGetSymbolAddress((void**)&sB1, g_sB1);
    cudaGetSymbolAddress((void**)&Mf, g_Mf);
    cudaGetSymbolAddress((void**)&Lf, g_Lf);
    cudaGetSymbolAddress((void**)&sM, g_sM);
    cudaGetSymbolAddress((void**)&sL, g_sL);
    cudaGetSymbolAddress((void**)&qW1a, g_qW1a);
    cudaGetSymbolAddress((void**)&qW1b, g_qW1b);
    cudaGetSymbolAddress((void**)&qB3a, g_qB3a);
    cudaGetSymbolAddress((void**)&qB3b, g_qB3b);
    cudaGetSymbolAddress((void**)&qB1a, g_qB1a);
    cudaGetSymbolAddress((void**)&qB1b, g_qB1b);
    cudaGetSymbolAddress((void**)&qMa, g_qMa);
    cudaGetSymbolAddress((void**)&qMb, g_qMb);
    cudaGetSymbolAddress((void**)&qLa, g_qLa);
    cudaGetSymbolAddress((void**)&qLb, g_qLb);

    cudaFuncSetAttribute(gemm_i8,
                         cudaFuncAttributeMaxDynamicSharedMemorySize, SMEM_GEMM_BYTES);

    // -------- weight prep --------
    transpose_f32_k<<<dim3(DD / 32, HH1 / 32), dim3(32, 8)>>>(W1, HH1, DD, W1T);
    quant_rows<16><<<DD * 32 / 256, 256>>>(W1T, qW1a, qW1b, sW1);

    // -------- forward pass --------
    fwd_kernel<<<dim3(HH1 / 32, BB / 4), 128>>>(x,  W1, b1,  c1, s1, nullptr, DD,  HH1, 1);
    fwd_kernel<<<dim3(HH2 / 32, BB / 4), 128>>>(c1, W2, b2,  c2, s2, out_c2,  HH1, HH2, 1);
    fwd_kernel<<<dim3(HH1 / 32, BB / 4), 128>>>(c2, W2, b3,  c3, s3, nullptr, HH2, HH1, 0);
    fwd_kernel<<<dim3(DD  / 32, BB / 4), 128>>>(c3, W1, b_r, out_rec, nullptr, nullptr, HH1, DD, 0);

    // -------- quantize B operands (per-b rows of W2*s) --------
    quant_B<<<BB * HH2 * 32 / 256, 256>>>(W2, s3, nullptr, qB3a, qB3b, sB3);
    quant_B<<<BB * HH2 * 32 / 256, 256>>>(W2, s1, s2,      qB1a, qB1b, sB1);

    // -------- GEMM A1: M1[b][d,e] = sum_h W1T[d,h]*s3[b,h]*W2[e,h] ----------
    gemm_i8<<<dim3(HH2 / 128, DD / 128, BB), 256, SMEM_GEMM_BYTES>>>(
        qW1a, qW1b, 0,
        qB3a, qB3b, (size_t)HH2 * HH1,
        sW1, 0,
        sB3, HH2, HH1,
        Mf, (size_t)HH2, (size_t)DD * HH2);

    // -------- GEMM A2: L[b][d,e] = (sum_h W1T*s1*W2) * s2[b,e] (s2 in sB1) ---
    gemm_i8<<<dim3(HH2 / 128, DD / 128, BB), 256, SMEM_GEMM_BYTES>>>(
        qW1a, qW1b, 0,
        qB1a, qB1b, (size_t)HH2 * HH1,
        sW1, 0,
        sB1, HH2, HH1,
        Lf, (size_t)HH2, (size_t)DD * HH2);

    // -------- quantize L and M1 rows for GEMM C --------
    quant_rows<8><<<BB * DD * 32 / 256, 256>>>(Lf, qLa, qLb, sL);
    quant_rows<8><<<BB * DD * 32 / 256, 256>>>(Mf, qMa, qMb, sM);

    // -------- GEMM C: Jac[b][d,d'] = sum_e L[b][d,e]*M1[b][d',e] -------------
    // flat offset(b,d,d') = d*(B*D) + b*D + d'  => ldc = B*D, strideC = D
    gemm_i8<<<dim3(DD / 128, DD / 128, BB), 256, SMEM_GEMM_BYTES>>>(
        qLa, qLb, (size_t)DD * HH2,
        qMa, qMb, (size_t)DD * HH2,
        sL, (size_t)DD,
        sM, DD, HH2,
        out_jac, (size_t)BB * DD, (size_t)DD);
}

// round 10
// speedup vs baseline: 2.1293x; 2.1293x over previous
#include <cuda_runtime.h>
#include <cuda_bf16.h>
#include <cstdint>

#define BB   128
#define DD   1024
#define HH1  512
#define HH2  256

typedef unsigned int u32;
typedef unsigned long long u64;

// ---------------- scratch (device globals; no allocation allowed) ----------
__device__ float g_c1[BB * HH1];
__device__ float g_s1[BB * HH1];
__device__ float g_c2[BB * HH2];
__device__ float g_s2[BB * HH2];
__device__ float g_c3[BB * HH1];
__device__ float g_s3[BB * HH1];
__device__ __nv_bfloat16 g_W1Thi[DD * HH1];              // W1^T hi  [1024,512]
__device__ __nv_bfloat16 g_W1Tlo[DD * HH1];              // W1^T lo
__device__ __nv_bfloat16 g_M1hi[(size_t)BB * DD * HH2];  // M1 pair [b][1024,256]
__device__ __nv_bfloat16 g_M1lo[(size_t)BB * DD * HH2];
__device__ __nv_bfloat16 g_Lhi[(size_t)BB * DD * HH2];   // L pair  [b][1024,256]
__device__ __nv_bfloat16 g_Llo[(size_t)BB * DD * HH2];

// ---------------- helpers ----------------------------------------------------
__device__ __forceinline__ u32 smem_u32(const void* p) {
    u32 a;
    asm("{ .reg .u64 t; cvta.to.shared.u64 t, %1; cvt.u32.u64 %0, t; }"
        : "=r"(a) : "l"(p));
    return a;
}

#define STS128(ad, v) \
    asm volatile("st.shared.v4.b32 [%0], {%1, %2, %3, %4};" \
                 :: "r"(ad), "r"((v).x), "r"((v).y), "r"((v).z), "r"((v).w) : "memory")

__device__ __forceinline__ void cpa16(u32 dst, const void* src) {
    asm volatile("cp.async.cg.shared.global [%0], [%1], 16;"
                 :: "r"(dst), "l"(src) : "memory");
}
#define CP_COMMIT() asm volatile("cp.async.commit_group;" ::: "memory")
#define CP_WAIT0()  asm volatile("cp.async.wait_group 0;" ::: "memory")

__device__ __forceinline__ void ldsm4(u32* r, u32 addr) {
    asm volatile("ldmatrix.sync.aligned.m8n8.x4.shared.b16 {%0,%1,%2,%3}, [%4];"
                 : "=r"(r[0]), "=r"(r[1]), "=r"(r[2]), "=r"(r[3]) : "r"(addr));
}

__device__ __forceinline__ void mma_bf16(float* c, const u32* a, const u32* b) {
    asm volatile("mma.sync.aligned.m16n8k16.row.col.f32.bf16.bf16.f32 "
                 "{%0,%1,%2,%3}, {%4,%5,%6,%7}, {%8,%9}, {%0,%1,%2,%3};"
                 : "+f"(c[0]), "+f"(c[1]), "+f"(c[2]), "+f"(c[3])
                 : "r"(a[0]), "r"(a[1]), "r"(a[2]), "r"(a[3]),
                   "r"(b[0]), "r"(b[1]));
}

// bf16 split: hi = rn(p) (bf16 bits), lo = p - hi (exact fp32)
__device__ __forceinline__ u32 split1(float p, float& lo) {
    u32 u = __float_as_uint(p);
    u32 r = (u + 0x7FFFu + ((u >> 16) & 1u)) & 0xFFFF0000u;
    lo = p - __uint_as_float(r);
    return r >> 16;
}
__device__ __forceinline__ u32 bf16rn(float p) {
    u32 u = __float_as_uint(p);
    return (u + 0x7FFFu + ((u >> 16) & 1u)) >> 16;
}

// ---------------- forward pass (2 samples/block) -----------------------------
__global__ void fwd_kernel(const float* __restrict__ A,
                           const float* __restrict__ W,
                           const float* __restrict__ bias,
                           float* __restrict__ c_out,
                           float* __restrict__ s_out,
                           float* __restrict__ extra_out,
                           int K, int N, int transW) {
    __shared__ float sA[2][1024];
    const int b0  = blockIdx.y * 2;
    const int tid = threadIdx.x;
    #pragma unroll
    for (int bi = 0; bi < 2; ++bi) {
        const float4* src = (const float4*)(A + (size_t)(b0 + bi) * K);
        float4* dst = (float4*)sA[bi];
        for (int k = tid; k < (K >> 2); k += 128) dst[k] = src[k];
    }
    __syncthreads();
    const int on = tid >> 2, kq = tid & 3;
    const int n  = blockIdx.x * 32 + on;
    const int kpt = K >> 2;
    const int k0  = kq * kpt;
    float acc[2] = {0.f, 0.f};
    if (transW) {
        const float* wr = W + (size_t)n * K + k0;
        #pragma unroll 4
        for (int k = 0; k < kpt; k += 4) {
            float4 w4 = *(const float4*)(wr + k);
            #pragma unroll
            for (int bi = 0; bi < 2; ++bi) {
                float4 x4 = *(const float4*)(&sA[bi][k0 + k]);
                acc[bi] += x4.x * w4.x + x4.y * w4.y + x4.z * w4.z + x4.w * w4.w;
            }
        }
    } else {
        #pragma unroll 4
        for (int k = 0; k < kpt; k += 4) {
            float w0 = W[(size_t)(k0 + k) * N + n];
            float w1 = W[(size_t)(k0 + k + 1) * N + n];
            float w2 = W[(size_t)(k0 + k + 2) * N + n];
            float w3 = W[(size_t)(k0 + k + 3) * N + n];
            #pragma unroll
            for (int bi = 0; bi < 2; ++bi) {
                acc[bi] += sA[bi][k0 + k] * w0 + sA[bi][k0 + k + 1] * w1
                         + sA[bi][k0 + k + 2] * w2 + sA[bi][k0 + k + 3] * w3;
            }
        }
    }
    #pragma unroll
    for (int bi = 0; bi < 2; ++bi) {
        acc[bi] += __shfl_xor_sync(0xFFFFFFFFu, acc[bi], 1);
        acc[bi] += __shfl_xor_sync(0xFFFFFFFFu, acc[bi], 2);
    }
    if (kq == 0) {
        const float bv = bias[n];
        #pragma unroll
        for (int bi = 0; bi < 2; ++bi) {
            const float c = 1.0f / (1.0f + expf(-(acc[bi] + bv)));
            const size_t o = (size_t)(b0 + bi) * N + n;
            if (c_out)     c_out[o]     = c;
            if (s_out)     s_out[o]     = c * (1.0f - c);
            if (extra_out) extra_out[o] = c;
        }
    }
}

// ---------------- one-time transpose+split of W1 (bf16 pair) -----------------
__global__ void transpose_split_k(const float* __restrict__ in, int R, int C,
                                  __nv_bfloat16* __restrict__ oh,
                                  __nv_bfloat16* __restrict__ ol) {
    __shared__ float t[32][33];
    const int c0 = blockIdx.x * 32, r0 = blockIdx.y * 32;
    const int tx = threadIdx.x, ty = threadIdx.y;
    #pragma unroll
    for (int i = 0; i < 32; i += 8)
        t[ty + i][tx] = in[(size_t)(r0 + ty + i) * C + c0 + tx];
    __syncthreads();
    #pragma unroll
    for (int i = 0; i < 32; i += 8) {
        float v = t[tx][ty + i];
        size_t o = (size_t)(c0 + ty + i) * R + r0 + tx;
        float lf; u32 h = split1(v, lf);
        ((unsigned short*)oh)[o] = (unsigned short)h;
        ((unsigned short*)ol)[o] = (unsigned short)bf16rn(lf);
    }
}

// ---------------- shared tile geometry ---------------------------------------
#define ROWP        80
#define A_MAT       (128 * ROWP)            // 10240
#define OFF_AL      A_MAT
#define OFF_BH      (2 * A_MAT)
#define OFF_BL      (3 * A_MAT)
#define STAGE_BYTES (4 * A_MAT)             // 40960
#define SMEM_GEMM_BYTES (2 * STAGE_BYTES)   // 81920

// ---------------- fused A GEMM (A1+A2): CTA 128x128, 2 CTA/SM ----------------
// variant = blockIdx.z >> 7  (0: s3 -> M1 pair; 1: s1, x s2 -> L pair)
// out[b][m,e] = (sum_h W1T[m,h]*sc[b,h]*W2[e,h]) * (variant ? s2[b,e] : 1)
__global__ void __launch_bounds__(128, 2)
gemm_A(const __nv_bfloat16* __restrict__ Ahi_g,
       const __nv_bfloat16* __restrict__ Alo_g,
       const float* __restrict__ W2g,
       const float* __restrict__ s3g, const float* __restrict__ s1g,
       const float* __restrict__ s2g,
       __nv_bfloat16* __restrict__ M1hi, __nv_bfloat16* __restrict__ M1lo,
       __nv_bfloat16* __restrict__ Lhi,  __nv_bfloat16* __restrict__ Llo) {
    extern __shared__ char smem[];
    const u32 sb  = smem_u32(smem);
    const int tid = threadIdx.x;
    const int wid = tid >> 5;
    const int lid = tid & 31;
    const int bz  = blockIdx.z;
    const int variant = bz >> 7;
    const int b   = bz & 127;
    const int n0  = blockIdx.x * 128;
    const int m0  = blockIdx.y * 128;
    const int K   = HH1;

    const float* sc_b = (variant ? s1g : s3g) + (size_t)b * K;
    __nv_bfloat16* Chi = variant ? Lhi : M1hi;
    __nv_bfloat16* Clo = variant ? Llo : M1lo;

    const int m0w = (wid & 1) * 64;
    const int n0w = (wid >> 1) * 64;

    const int r = tid;
    const size_t aRow = (size_t)(m0 + r) * K;
    const size_t bRow = (size_t)(n0 + r) * K;
    const u32 stoff = (u32)r * ROWP;

    const int l = lid;
    const u32 a_base = (u32)((m0w + (l & 7) + ((l >> 3) & 1) * 8) * ROWP
                             + ((l >> 4) & 1) * 16);
    const int mt = l >> 3;
    const u32 b_base = (u32)((n0w + ((mt >> 1) & 1) * 8 + (l & 7)) * ROWP
                             + (mt & 1) * 16);

    float acc[4][8][4];
    #pragma unroll
    for (int i = 0; i < 4; i++)
        #pragma unroll
        for (int j = 0; j < 8; j++)
            #pragma unroll
            for (int q = 0; q < 4; q++) acc[i][j][q] = 0.f;

    u32 hw[16], lw[16];

    auto issue_A = [&](int sidx, int kt) {
        const u32 stg = sb + (u32)sidx * STAGE_BYTES + stoff;
        const char* ph = (const char*)(Ahi_g + aRow + kt);
        const char* pl = (const char*)(Alo_g + aRow + kt);
        #pragma unroll
        for (int j = 0; j < 4; ++j) cpa16(stg + j * 16, ph + j * 16);
        #pragma unroll
        for (int j = 0; j < 4; ++j) cpa16(stg + OFF_AL + j * 16, pl + j * 16);
        CP_COMMIT();
    };

    auto ldg_split = [&](int kt) {
        const float4* pb = (const float4*)(W2g + bRow + kt);
        const float4* ps = (const float4*)(sc_b + kt);
        #pragma unroll
        for (int j = 0; j < 8; ++j) {
            float4 bv = pb[j];
            float4 sv = ps[j];
            float p0 = bv.x * sv.x, p1 = bv.y * sv.y;
            float p2 = bv.z * sv.z, p3 = bv.w * sv.w;
            float l0, l1, l2, l3;
            u32 h0 = split1(p0, l0), h1 = split1(p1, l1);
            u32 h2 = split1(p2, l2), h3 = split1(p3, l3);
            hw[j * 2 + 0] = h0 | (h1 << 16);
            hw[j * 2 + 1] = h2 | (h3 << 16);
            lw[j * 2 + 0] = bf16rn(l0) | (bf16rn(l1) << 16);
            lw[j * 2 + 1] = bf16rn(l2) | (bf16rn(l3) << 16);
        }
    };

    const int niter = K >> 5;
    issue_A(0, 0);
    ldg_split(0);

    for (int it = 0; it < niter; ++it) {
        const u32 stg = sb + (u32)(it & 1) * STAGE_BYTES;
        {
            const u32 d = stg + stoff;
            #pragma unroll
            for (int j = 0; j < 4; ++j) {
                uint4 vh = make_uint4(hw[4*j], hw[4*j+1], hw[4*j+2], hw[4*j+3]);
                uint4 vl = make_uint4(lw[4*j], lw[4*j+1], lw[4*j+2], lw[4*j+3]);
                STS128(d + OFF_BH + 16 * j, vh);
                STS128(d + OFF_BL + 16 * j, vl);
            }
        }
        CP_WAIT0();
        __syncthreads();
        if (it + 1 < niter) {
            issue_A((it + 1) & 1, (it + 1) << 5);
            ldg_split((it + 1) << 5);
        }

        const u32 aH = stg + a_base;
        const u32 aL = stg + OFF_AL + a_base;
        const u32 bH = stg + OFF_BH + b_base;
        const u32 bL = stg + OFF_BL + b_base;

        #pragma unroll
        for (int ks = 0; ks < 2; ++ks) {
            u32 Ah[4][4], Al[4][4];
            #pragma unroll
            for (int mi = 0; mi < 4; ++mi) {
                ldsm4(Ah[mi], aH + mi * (16 * ROWP) + ks * 32);
                ldsm4(Al[mi], aL + mi * (16 * ROWP) + ks * 32);
            }
            #pragma unroll
            for (int jj = 0; jj < 4; ++jj) {
                u32 Bh[4], Bl[4];
                ldsm4(Bh, bH + jj * (16 * ROWP) + ks * 32);
                ldsm4(Bl, bL + jj * (16 * ROWP) + ks * 32);
                #pragma unroll
                for (int mi = 0; mi < 4; ++mi) {
                    mma_bf16(acc[mi][2 * jj],     Ah[mi], &Bh[0]);
                    mma_bf16(acc[mi][2 * jj + 1], Ah[mi], &Bh[2]);
                    mma_bf16(acc[mi][2 * jj],     Ah[mi], &Bl[0]);
                    mma_bf16(acc[mi][2 * jj + 1], Ah[mi], &Bl[2]);
                    mma_bf16(acc[mi][2 * jj],     Al[mi], &Bh[0]);
                    mma_bf16(acc[mi][2 * jj + 1], Al[mi], &Bh[2]);
                }
            }
        }
    }

    // ---- epilogue: optional s2 scale, split to bf16 pair ----
    const int gid = lid >> 2;
    const int tig = lid & 3;
    const float* es = s2g + (size_t)b * HH2;
    #pragma unroll
    for (int mi = 0; mi < 4; ++mi) {
        #pragma unroll
        for (int nj = 0; nj < 8; ++nj) {
            const int row = m0 + m0w + 16 * mi + gid;
            const int col = n0 + n0w + 8 * nj + tig * 2;
            float a[4] = { acc[mi][nj][0], acc[mi][nj][1],
                           acc[mi][nj][2], acc[mi][nj][3] };
            if (variant) {
                const float e0 = es[col], e1 = es[col + 1];
                a[0] *= e0; a[1] *= e1; a[2] *= e0; a[3] *= e1;
            }
            const size_t o0 = (size_t)b * ((size_t)DD * HH2)
                            + (size_t)row * HH2 + col;
            const size_t o1 = o0 + 8 * HH2;
            float l0, l1, l2, l3;
            u32 h0 = split1(a[0], l0), h1 = split1(a[1], l1);
            u32 h2 = split1(a[2], l2), h3 = split1(a[3], l3);
            *(u32*)(Chi + o0) = h0 | (h1 << 16);
            *(u32*)(Clo + o0) = bf16rn(l0) | (bf16rn(l1) << 16);
            *(u32*)(Chi + o1) = h2 | (h3 << 16);
            *(u32*)(Clo + o1) = bf16rn(l2) | (bf16rn(l3) << 16);
        }
    }
}

// ---------------- C GEMM: both operands bf16 pairs, fp32 out -----------------
// Jac[b][m,n] = sum_k L[b][m,k] * M1[b][n,k]   (K = 256)
__global__ void __launch_bounds__(128, 2)
gemm_C(const __nv_bfloat16* __restrict__ Ahi_g,
       const __nv_bfloat16* __restrict__ Alo_g,
       const __nv_bfloat16* __restrict__ Bhi_g,
       const __nv_bfloat16* __restrict__ Blo_g,
       float* __restrict__ Cf, size_t ldc, size_t strideC) {
    extern __shared__ char smem[];
    const u32 sb  = smem_u32(smem);
    const int tid = threadIdx.x;
    const int wid = tid >> 5;
    const int lid = tid & 31;
    const int b   = blockIdx.z;
    const int n0  = blockIdx.x * 128;
    const int m0  = blockIdx.y * 128;
    const int K   = HH2;
    const size_t strideAB = (size_t)DD * HH2;

    const int m0w = (wid & 1) * 64;
    const int n0w = (wid >> 1) * 64;

    const int r = tid;
    const size_t aRow = (size_t)b * strideAB + (size_t)(m0 + r) * K;
    const size_t bRow = (size_t)b * strideAB + (size_t)(n0 + r) * K;
    const u32 stoff = (u32)r * ROWP;

    const int l = lid;
    const u32 a_base = (u32)((m0w + (l & 7) + ((l >> 3) & 1) * 8) * ROWP
                             + ((l >> 4) & 1) * 16);
    const int mt = l >> 3;
    const u32 b_base = (u32)((n0w + ((mt >> 1) & 1) * 8 + (l & 7)) * ROWP
                             + (mt & 1) * 16);

    float acc[4][8][4];
    #pragma unroll
    for (int i = 0; i < 4; i++)
        #pragma unroll
        for (int j = 0; j < 8; j++)
            #pragma unroll
            for (int q = 0; q < 4; q++) acc[i][j][q] = 0.f;

    auto issue_stage = [&](int sidx, int kt) {
        const u32 stg = sb + (u32)sidx * STAGE_BYTES + stoff;
        const char* ph = (const char*)(Ahi_g + aRow + kt);
        const char* pl = (const char*)(Alo_g + aRow + kt);
        const char* qh = (const char*)(Bhi_g + bRow + kt);
        const char* ql = (const char*)(Blo_g + bRow + kt);
        #pragma unroll
        for (int j = 0; j < 4; ++j) cpa16(stg + j * 16, ph + j * 16);
        #pragma unroll
        for (int j = 0; j < 4; ++j) cpa16(stg + OFF_AL + j * 16, pl + j * 16);
        #pragma unroll
        for (int j = 0; j < 4; ++j) cpa16(stg + OFF_BH + j * 16, qh + j * 16);
        #pragma unroll
        for (int j = 0; j < 4; ++j) cpa16(stg + OFF_BL + j * 16, ql + j * 16);
        CP_COMMIT();
    };

    const int niter = K >> 5;
    issue_stage(0, 0);

    for (int it = 0; it < niter; ++it) {
        const u32 stg = sb + (u32)(it & 1) * STAGE_BYTES;
        CP_WAIT0();
        __syncthreads();
        if (it + 1 < niter) issue_stage((it + 1) & 1, (it + 1) << 5);

        const u32 aH = stg + a_base;
        const u32 aL = stg + OFF_AL + a_base;
        const u32 bH = stg + OFF_BH + b_base;
        const u32 bL = stg + OFF_BL + b_base;

        #pragma unroll
        for (int ks = 0; ks < 2; ++ks) {
            u32 Ah[4][4], Al[4][4];
            #pragma unroll
            for (int mi = 0; mi < 4; ++mi) {
                ldsm4(Ah[mi], aH + mi * (16 * ROWP) + ks * 32);
                ldsm4(Al[mi], aL + mi * (16 * ROWP) + ks * 32);
            }
            #pragma unroll
            for (int jj = 0; jj < 4; ++jj) {
                u32 Bh[4], Bl[4];
                ldsm4(Bh, bH + jj * (16 * ROWP) + ks * 32);
                ldsm4(Bl, bL + jj * (16 * ROWP) + ks * 32);
                #pragma unroll
                for (int mi = 0; mi < 4; ++mi) {
                    mma_bf16(acc[mi][2 * jj],     Ah[mi], &Bh[0]);
                    mma_bf16(acc[mi][2 * jj + 1], Ah[mi], &Bh[2]);
                    mma_bf16(acc[mi][2 * jj],     Ah[mi], &Bl[0]);
                    mma_bf16(acc[mi][2 * jj + 1], Ah[mi], &Bl[2]);
                    mma_bf16(acc[mi][2 * jj],     Al[mi], &Bh[0]);
                    mma_bf16(acc[mi][2 * jj + 1], Al[mi], &Bh[2]);
                }
            }
        }
        __syncthreads();
    }

    const int gid = lid >> 2;
    const int tig = lid & 3;
    #pragma unroll
    for (int mi = 0; mi < 4; ++mi) {
        #pragma unroll
        for (int nj = 0; nj < 8; ++nj) {
            const int row = m0 + m0w + 16 * mi + gid;
            const int col = n0 + n0w + 8 * nj + tig * 2;
            const float* a = acc[mi][nj];
            const size_t o0 = (size_t)b * strideC + (size_t)row * ldc + col;
            const size_t o1 = o0 + 8 * ldc;
            *(float2*)(Cf + o0) = make_float2(a[0], a[1]);
            *(float2*)(Cf + o1) = make_float2(a[2], a[3]);
        }
    }
}

// ---------------- launcher ---------------------------------------------------
extern "C" void kernel_launch(void* const* d_in, const int* in_sizes, int n_in,
                              void* d_out, int out_size) {
    const float* x   = (const float*)d_in[0];
    const float* W1  = (const float*)d_in[1];
    const float* b1  = (const float*)d_in[2];
    const float* W2  = (const float*)d_in[3];
    const float* b2  = (const float*)d_in[4];
    const float* b3  = (const float*)d_in[5];
    const float* b_r = (const float*)d_in[6];

    float* out     = (float*)d_out;
    float* out_rec = out;                           // [128,1024]
    float* out_c2  = out + (size_t)BB * DD;         // [128,256]
    float* out_jac = out_c2 + (size_t)BB * HH2;     // [D, B, D] flat

    float *c1, *s1, *c2, *s2, *c3, *s3;
    __nv_bfloat16 *W1Thi, *W1Tlo, *M1hi, *M1lo, *Lhi, *Llo;
    cudaGetSymbolAddress((void**)&c1, g_c1);
    cudaGetSymbolAddress((void**)&s1, g_s1);
    cudaGetSymbolAddress((void**)&c2, g_c2);
    cudaGetSymbolAddress((void**)&s2, g_s2);
    cudaGetSymbolAddress((void**)&c3, g_c3);
    cudaGetSymbolAddress((void**)&s3, g_s3);
    cudaGetSymbolAddress((void**)&W1Thi, g_W1Thi);
    cudaGetSymbolAddress((void**)&W1Tlo, g_W1Tlo);
    cudaGetSymbolAddress((void**)&M1hi, g_M1hi);
    cudaGetSymbolAddress((void**)&M1lo, g_M1lo);
    cudaGetSymbolAddress((void**)&Lhi, g_Lhi);
    cudaGetSymbolAddress((void**)&Llo, g_Llo);

    cudaFuncSetAttribute(gemm_A,
                         cudaFuncAttributeMaxDynamicSharedMemorySize, SMEM_GEMM_BYTES);
    cudaFuncSetAttribute(gemm_C,
                         cudaFuncAttributeMaxDynamicSharedMemorySize, SMEM_GEMM_BYTES);

    // -------- weight prep (tiny) --------
    transpose_split_k<<<dim3(DD / 32, HH1 / 32), dim3(32, 8)>>>(W1, HH1, DD, W1Thi, W1Tlo);

    // -------- forward pass --------
    fwd_kernel<<<dim3(HH1 / 32, BB / 2), 128>>>(x,  W1, b1,  c1, s1, nullptr, DD,  HH1, 1);
    fwd_kernel<<<dim3(HH2 / 32, BB / 2), 128>>>(c1, W2, b2,  c2, s2, out_c2,  HH1, HH2, 1);
    fwd_kernel<<<dim3(HH1 / 32, BB / 2), 128>>>(c2, W2, b3,  c3, s3, nullptr, HH2, HH1, 0);
    fwd_kernel<<<dim3(DD  / 32, BB / 2), 128>>>(c3, W1, b_r, out_rec, nullptr, nullptr, HH1, DD, 0);

    // -------- fused A1+A2 (bf16 3-product HMMA) --------
    // z < 128: M1[b][d,e] = sum_h W1T*s3*W2      -> M1 pair
    // z >=128: L[b][d,e]  = (sum_h W1T*s1*W2)*s2 -> L pair
    gemm_A<<<dim3(HH2 / 128, DD / 128, 2 * BB), 128, SMEM_GEMM_BYTES>>>(
        W1Thi, W1Tlo, W2, s3, s1, s2, M1hi, M1lo, Lhi, Llo);

    // -------- C: Jac[b][d,d'] = sum_e L[b][d,e]*M1[b][d',e] ------------------
    // flat offset(b,d,d') = d*(B*D) + b*D + d'  => ldc = B*D, strideC = D
    gemm_C<<<dim3(DD / 128, DD / 128, BB), 128, SMEM_GEMM_BYTES>>>(
        Lhi, Llo, M1hi, M1lo,
        out_jac, (size_t)BB * DD, (size_t)DD);
}

// round 12
// speedup vs baseline: 2.2440x; 1.0539x over previous
#include <cuda_runtime.h>
#include <cuda_bf16.h>
#include <cstdint>

#define BB   128
#define DD   1024
#define HH1  512
#define HH2  256

typedef unsigned int u32;
typedef unsigned long long u64;

// ---------------- scratch (device globals; no allocation allowed) ----------
__device__ float g_c1[BB * HH1];
__device__ float g_s1[BB * HH1];
__device__ float g_c2[BB * HH2];
__device__ float g_s2[BB * HH2];
__device__ float g_c3[BB * HH1];
__device__ float g_s3[BB * HH1];
__device__ __nv_bfloat16 g_W1Thi[DD * HH1];              // W1^T hi  [1024,512]
__device__ __nv_bfloat16 g_W1Tlo[DD * HH1];              // W1^T lo
__device__ __nv_bfloat16 g_M1hi[(size_t)BB * DD * HH2];  // M1 pair [b][1024,256]
__device__ __nv_bfloat16 g_M1lo[(size_t)BB * DD * HH2];
__device__ __nv_bfloat16 g_Lhi[(size_t)BB * DD * HH2];   // L pair  [b][1024,256]
__device__ __nv_bfloat16 g_Llo[(size_t)BB * DD * HH2];

// ---------------- helpers ----------------------------------------------------
__device__ __forceinline__ u32 smem_u32(const void* p) {
    u32 a;
    asm("{ .reg .u64 t; cvta.to.shared.u64 t, %1; cvt.u32.u64 %0, t; }"
        : "=r"(a) : "l"(p));
    return a;
}

#define STS128(ad, v) \
    asm volatile("st.shared.v4.b32 [%0], {%1, %2, %3, %4};" \
                 :: "r"(ad), "r"((v).x), "r"((v).y), "r"((v).z), "r"((v).w) : "memory")

__device__ __forceinline__ void cpa16(u32 dst, const void* src) {
    asm volatile("cp.async.cg.shared.global [%0], [%1], 16;"
                 :: "r"(dst), "l"(src) : "memory");
}
#define CP_COMMIT() asm volatile("cp.async.commit_group;" ::: "memory")
#define CP_WAIT0()  asm volatile("cp.async.wait_group 0;" ::: "memory")

__device__ __forceinline__ void ldsm4(u32* r, u32 addr) {
    asm volatile("ldmatrix.sync.aligned.m8n8.x4.shared.b16 {%0,%1,%2,%3}, [%4];"
                 : "=r"(r[0]), "=r"(r[1]), "=r"(r[2]), "=r"(r[3]) : "r"(addr));
}

__device__ __forceinline__ void mma_bf16(float* c, const u32* a, const u32* b) {
    asm volatile("mma.sync.aligned.m16n8k16.row.col.f32.bf16.bf16.f32 "
                 "{%0,%1,%2,%3}, {%4,%5,%6,%7}, {%8,%9}, {%0,%1,%2,%3};"
                 : "+f"(c[0]), "+f"(c[1]), "+f"(c[2]), "+f"(c[3])
                 : "r"(a[0]), "r"(a[1]), "r"(a[2]), "r"(a[3]),
                   "r"(b[0]), "r"(b[1]));
}

// bf16 split: hi = rn(p) (bf16 bits), lo = p - hi (exact fp32)
__device__ __forceinline__ u32 split1(float p, float& lo) {
    u32 u = __float_as_uint(p);
    u32 r = (u + 0x7FFFu + ((u >> 16) & 1u)) & 0xFFFF0000u;
    lo = p - __uint_as_float(r);
    return r >> 16;
}
__device__ __forceinline__ u32 bf16rn(float p) {
    u32 u = __float_as_uint(p);
    return (u + 0x7FFFu + ((u >> 16) & 1u)) >> 16;
}

// ---------------- forward pass, row-major W (C = sig(A @ W^T + b)) -----------
// One warp per output n, lanes stride along K (fully coalesced), 4 samples.
// grid (N/4, B/4), block 128.
__global__ void fwd_w1(const float* __restrict__ A,
                       const float* __restrict__ W,
                       const float* __restrict__ bias,
                       float* __restrict__ c_out,
                       float* __restrict__ s_out,
                       float* __restrict__ extra_out,
                       int K, int N) {
    const int lane = threadIdx.x & 31;
    const int w    = threadIdx.x >> 5;
    const int n    = blockIdx.x * 4 + w;
    const int b0   = blockIdx.y * 4;
    const int K4   = K >> 2;
    const float4* W4 = (const float4*)(W + (size_t)n * K);
    const float4* X4 = (const float4*)(A + (size_t)b0 * K);
    float acc[4] = {0.f, 0.f, 0.f, 0.f};
    const int nit = K4 >> 5;            // 8 (K=1024) or 4 (K=512)
    #pragma unroll 4
    for (int ii = 0; ii < nit; ++ii) {
        const int i = ii * 32 + lane;
        float4 wv = W4[i];
        #pragma unroll
        for (int bi = 0; bi < 4; ++bi) {
            float4 xv = X4[(size_t)bi * K4 + i];
            acc[bi] += xv.x * wv.x + xv.y * wv.y + xv.z * wv.z + xv.w * wv.w;
        }
    }
    #pragma unroll
    for (int bi = 0; bi < 4; ++bi)
        #pragma unroll
        for (int o = 16; o; o >>= 1)
            acc[bi] += __shfl_xor_sync(0xFFFFFFFFu, acc[bi], o);
    if (lane == 0) {
        const float bv = bias[n];
        #pragma unroll
        for (int bi = 0; bi < 4; ++bi) {
            const float c = 1.0f / (1.0f + expf(-(acc[bi] + bv)));
            const size_t o = (size_t)(b0 + bi) * N + n;
            if (c_out)     c_out[o]     = c;
            if (s_out)     s_out[o]     = c * (1.0f - c);
            if (extra_out) extra_out[o] = c;
        }
    }
}

// ---------------- forward pass, col-major W (C = sig(A @ W + b)) -------------
// Lanes cover 32 consecutive n per k (coalesced); warps split K 4 ways;
// x rows in SMEM (broadcast); SMEM reduce. grid (N/32, B/4), block 128.
__global__ void fwd_w0(const float* __restrict__ A,
                       const float* __restrict__ W,
                       const float* __restrict__ bias,
                       float* __restrict__ c_out,
                       float* __restrict__ s_out,
                       int K, int N) {
    __shared__ float sA[4][512];
    __shared__ float sRed[4][4][32];
    const int tid  = threadIdx.x;
    const int lane = tid & 31;
    const int w    = tid >> 5;
    const int b0   = blockIdx.y * 4;
    const int n    = blockIdx.x * 32 + lane;
    const int K4   = K >> 2;
    for (int idx = tid; idx < 4 * K4; idx += 128) {
        const int bi = idx / K4, k4 = idx - bi * K4;
        ((float4*)sA[bi])[k4] = ((const float4*)(A + (size_t)(b0 + bi) * K))[k4];
    }
    __syncthreads();
    const int kpt = K >> 2;             // per warp: 64 (K=256) / 128 (K=512)
    const int kb  = w * kpt;
    const float* Wp = W + (size_t)kb * N + blockIdx.x * 32 + lane;
    float acc[4] = {0.f, 0.f, 0.f, 0.f};
    #pragma unroll 4
    for (int k = 0; k < kpt; ++k) {
        const float wv = Wp[(size_t)k * N];
        #pragma unroll
        for (int bi = 0; bi < 4; ++bi) acc[bi] += sA[bi][kb + k] * wv;
    }
    #pragma unroll
    for (int bi = 0; bi < 4; ++bi) sRed[w][bi][lane] = acc[bi];
    __syncthreads();
    const int bi = w;
    float r = sRed[0][bi][lane] + sRed[1][bi][lane]
            + sRed[2][bi][lane] + sRed[3][bi][lane];
    r += bias[n];
    const float c = 1.0f / (1.0f + expf(-r));
    const size_t o = (size_t)(b0 + bi) * N + n;
    if (c_out) c_out[o] = c;
    if (s_out) s_out[o] = c * (1.0f - c);
}

// ---------------- one-time transpose+split of W1 (bf16 pair) -----------------
__global__ void transpose_split_k(const float* __restrict__ in, int R, int C,
                                  __nv_bfloat16* __restrict__ oh,
                                  __nv_bfloat16* __restrict__ ol) {
    __shared__ float t[32][33];
    const int c0 = blockIdx.x * 32, r0 = blockIdx.y * 32;
    const int tx = threadIdx.x, ty = threadIdx.y;
    #pragma unroll
    for (int i = 0; i < 32; i += 8)
        t[ty + i][tx] = in[(size_t)(r0 + ty + i) * C + c0 + tx];
    __syncthreads();
    #pragma unroll
    for (int i = 0; i < 32; i += 8) {
        float v = t[tx][ty + i];
        size_t o = (size_t)(c0 + ty + i) * R + r0 + tx;
        float lf; u32 h = split1(v, lf);
        ((unsigned short*)oh)[o] = (unsigned short)h;
        ((unsigned short*)ol)[o] = (unsigned short)bf16rn(lf);
    }
}

// ---------------- HMMA split-bf16 batched GEMM, CTA 128x128, 2 CTA/SM --------
// out[b][m, n] = sum_k A[b][m,k] * (loader scale) * B[b][n,k]
// A: bf16 hi/lo pair (cp.async). B: fp32 + scale-split (B_PAIR=0, reg-staged)
// or bf16 pair (B_PAIR=1, cp.async). Warp tile 64x64, 4 warps (2M x 2N), BK=32.
#define ROWP        80
#define A_MAT       (128 * ROWP)            // 10240
#define OFF_AL      A_MAT
#define OFF_BH      (2 * A_MAT)
#define OFF_BL      (3 * A_MAT)
#define STAGE_BYTES (4 * A_MAT)             // 40960
#define SMEM_GEMM_BYTES (2 * STAGE_BYTES)   // 81920

template <bool OUT_PAIR, bool B_PAIR, bool EPI_SCALE>
__global__ void __launch_bounds__(128, 2)
gemm_split(const __nv_bfloat16* __restrict__ Ahi_g,
           const __nv_bfloat16* __restrict__ Alo_g, size_t strideA,
           const float* __restrict__ Bf_g,
           const __nv_bfloat16* __restrict__ Bhi_g,
           const __nv_bfloat16* __restrict__ Blo_g, size_t strideB,
           const float* __restrict__ sc_g, int K,
           const float* __restrict__ episc_g, int epiN,
           float* __restrict__ Cf,
           __nv_bfloat16* __restrict__ Chi, __nv_bfloat16* __restrict__ Clo,
           size_t ldc, size_t strideC) {
    extern __shared__ char smem[];
    const u32 sb  = smem_u32(smem);
    const int tid = threadIdx.x;
    const int wid = tid >> 5;
    const int lid = tid & 31;
    const int b   = blockIdx.z;
    const int n0  = blockIdx.x * 128;
    const int m0  = blockIdx.y * 128;

    const int m0w = (wid & 1) * 64;          // 2 warps in M
    const int n0w = (wid >> 1) * 64;         // 2 warps in N

    const __nv_bfloat16* Ahi_b = Ahi_g + (size_t)b * strideA;
    const __nv_bfloat16* Alo_b = Alo_g + (size_t)b * strideA;

    // loader: one tile row per thread
    const int r = tid;
    const size_t aRow = (size_t)(m0 + r) * K;
    const size_t bRow = (size_t)(n0 + r) * K;
    const u32 stoff = (u32)r * ROWP;

    // ldmatrix lane address bases
    const int l = lid;
    const u32 a_base = (u32)((m0w + (l & 7) + ((l >> 3) & 1) * 8) * ROWP
                             + ((l >> 4) & 1) * 16);
    const int mt = l >> 3;
    const u32 b_base = (u32)((n0w + ((mt >> 1) & 1) * 8 + (l & 7)) * ROWP
                             + (mt & 1) * 16);

    float acc[4][8][4];
    #pragma unroll
    for (int i = 0; i < 4; i++)
        #pragma unroll
        for (int j = 0; j < 8; j++)
            #pragma unroll
            for (int q = 0; q < 4; q++) acc[i][j][q] = 0.f;

    u32 hw[16], lw[16];                       // split staging (B_PAIR=0)

    auto issue_stage = [&](int sidx, int kt) {
        const u32 stg = sb + (u32)sidx * STAGE_BYTES + stoff;
        const char* ph = (const char*)(Ahi_b + aRow + kt);
        const char* pl = (const char*)(Alo_b + aRow + kt);
        #pragma unroll
        for (int j = 0; j < 4; ++j) cpa16(stg + j * 16, ph + j * 16);
        #pragma unroll
        for (int j = 0; j < 4; ++j) cpa16(stg + OFF_AL + j * 16, pl + j * 16);
        if (B_PAIR) {
            const char* qh = (const char*)(Bhi_g + (size_t)b * strideB + bRow + kt);
            const char* ql = (const char*)(Blo_g + (size_t)b * strideB + bRow + kt);
            #pragma unroll
            for (int j = 0; j < 4; ++j) cpa16(stg + OFF_BH + j * 16, qh + j * 16);
            #pragma unroll
            for (int j = 0; j < 4; ++j) cpa16(stg + OFF_BL + j * 16, ql + j * 16);
        }
        CP_COMMIT();
    };

    auto ldg_split = [&](int kt) {
        if (!B_PAIR) {
            const float4* pb = (const float4*)(Bf_g + (size_t)b * strideB + bRow + kt);
            const float4* ps = (const float4*)(sc_g + (size_t)b * K + kt);
            #pragma unroll
            for (int j = 0; j < 8; ++j) {
                float4 bv = pb[j];
                float4 sv = ps[j];
                float p0 = bv.x * sv.x, p1 = bv.y * sv.y;
                float p2 = bv.z * sv.z, p3 = bv.w * sv.w;
                float l0, l1, l2, l3;
                u32 h0 = split1(p0, l0), h1 = split1(p1, l1);
                u32 h2 = split1(p2, l2), h3 = split1(p3, l3);
                hw[j * 2 + 0] = h0 | (h1 << 16);
                hw[j * 2 + 1] = h2 | (h3 << 16);
                lw[j * 2 + 0] = bf16rn(l0) | (bf16rn(l1) << 16);
                lw[j * 2 + 1] = bf16rn(l2) | (bf16rn(l3) << 16);
            }
        }
    };

    const int niter = K >> 5;
    issue_stage(0, 0);
    ldg_split(0);

    for (int it = 0; it < niter; ++it) {
        const u32 stg = sb + (u32)(it & 1) * STAGE_BYTES;
        if (!B_PAIR) {
            const u32 d = stg + stoff;
            #pragma unroll
            for (int j = 0; j < 4; ++j) {
                uint4 vh = make_uint4(hw[4*j], hw[4*j+1], hw[4*j+2], hw[4*j+3]);
                uint4 vl = make_uint4(lw[4*j], lw[4*j+1], lw[4*j+2], lw[4*j+3]);
                STS128(d + OFF_BH + 16 * j, vh);
                STS128(d + OFF_BL + 16 * j, vl);
            }
        }
        CP_WAIT0();
        __syncthreads();
        if (it + 1 < niter) {
            issue_stage((it + 1) & 1, (it + 1) << 5);
            ldg_split((it + 1) << 5);
        }

        const u32 aH = stg + a_base;
        const u32 aL = stg + OFF_AL + a_base;
        const u32 bH = stg + OFF_BH + b_base;
        const u32 bL = stg + OFF_BL + b_base;

        #pragma unroll
        for (int ks = 0; ks < 2; ++ks) {
            u32 Ah[4][4], Al[4][4];
            #pragma unroll
            for (int mi = 0; mi < 4; ++mi) {
                ldsm4(Ah[mi], aH + mi * (16 * ROWP) + ks * 32);
                ldsm4(Al[mi], aL + mi * (16 * ROWP) + ks * 32);
            }
            #pragma unroll
            for (int jj = 0; jj < 4; ++jj) {
                u32 Bh[4], Bl[4];
                ldsm4(Bh, bH + jj * (16 * ROWP) + ks * 32);
                ldsm4(Bl, bL + jj * (16 * ROWP) + ks * 32);
                #pragma unroll
                for (int mi = 0; mi < 4; ++mi) {
                    mma_bf16(acc[mi][2 * jj],     Ah[mi], &Bh[0]);
                    mma_bf16(acc[mi][2 * jj + 1], Ah[mi], &Bh[2]);
                    mma_bf16(acc[mi][2 * jj],     Ah[mi], &Bl[0]);
                    mma_bf16(acc[mi][2 * jj + 1], Ah[mi], &Bl[2]);
                    mma_bf16(acc[mi][2 * jj],     Al[mi], &Bh[0]);
                    mma_bf16(acc[mi][2 * jj + 1], Al[mi], &Bh[2]);
                }
            }
        }
    }

    // ---- epilogue ----
    const int gid = lid >> 2;
    const int tig = lid & 3;
    #pragma unroll
    for (int mi = 0; mi < 4; ++mi) {
        #pragma unroll
        for (int nj = 0; nj < 8; ++nj) {
            const int row = m0 + m0w + 16 * mi + gid;
            const int col = n0 + n0w + 8 * nj + tig * 2;
            float a[4] = { acc[mi][nj][0], acc[mi][nj][1],
                           acc[mi][nj][2], acc[mi][nj][3] };
            if (EPI_SCALE) {
                const float* es = episc_g + (size_t)b * epiN + col;
                const float s0 = es[0], s1 = es[1];
                a[0] *= s0; a[1] *= s1; a[2] *= s0; a[3] *= s1;
            }
            const size_t o0 = (size_t)b * strideC + (size_t)row * ldc + col;
            const size_t o1 = o0 + 8 * ldc;
            if (OUT_PAIR) {
                float l0, l1, l2, l3;
                u32 h0 = split1(a[0], l0), h1 = split1(a[1], l1);
                u32 h2 = split1(a[2], l2), h3 = split1(a[3], l3);
                *(u32*)(Chi + o0) = h0 | (h1 << 16);
                *(u32*)(Clo + o0) = bf16rn(l0) | (bf16rn(l1) << 16);
                *(u32*)(Chi + o1) = h2 | (h3 << 16);
                *(u32*)(Clo + o1) = bf16rn(l2) | (bf16rn(l3) << 16);
            } else {
                *(float2*)(Cf + o0) = make_float2(a[0], a[1]);
                *(float2*)(Cf + o1) = make_float2(a[2], a[3]);
            }
        }
    }
}

// ---------------- launcher ---------------------------------------------------
extern "C" void kernel_launch(void* const* d_in, const int* in_sizes, int n_in,
                              void* d_out, int out_size) {
    const float* x   = (const float*)d_in[0];
    const float* W1  = (const float*)d_in[1];
    const float* b1  = (const float*)d_in[2];
    const float* W2  = (const float*)d_in[3];
    const float* b2  = (const float*)d_in[4];
    const float* b3  = (const float*)d_in[5];
    const float* b_r = (const float*)d_in[6];

    float* out     = (float*)d_out;
    float* out_rec = out;                           // [128,1024]
    float* out_c2  = out + (size_t)BB * DD;         // [128,256]
    float* out_jac = out_c2 + (size_t)BB * HH2;     // [D, B, D] flat

    float *c1, *s1, *c2, *s2, *c3, *s3;
    __nv_bfloat16 *W1Thi, *W1Tlo, *M1hi, *M1lo, *Lhi, *Llo;
    cudaGetSymbolAddress((void**)&c1, g_c1);
    cudaGetSymbolAddress((void**)&s1, g_s1);
    cudaGetSymbolAddress((void**)&c2, g_c2);
    cudaGetSymbolAddress((void**)&s2, g_s2);
    cudaGetSymbolAddress((void**)&c3, g_c3);
    cudaGetSymbolAddress((void**)&s3, g_s3);
    cudaGetSymbolAddress((void**)&W1Thi, g_W1Thi);
    cudaGetSymbolAddress((void**)&W1Tlo, g_W1Tlo);
    cudaGetSymbolAddress((void**)&M1hi, g_M1hi);
    cudaGetSymbolAddress((void**)&M1lo, g_M1lo);
    cudaGetSymbolAddress((void**)&Lhi, g_Lhi);
    cudaGetSymbolAddress((void**)&Llo, g_Llo);

    cudaFuncSetAttribute(gemm_split<true, false, false>,
                         cudaFuncAttributeMaxDynamicSharedMemorySize, SMEM_GEMM_BYTES);
    cudaFuncSetAttribute(gemm_split<true, false, true>,
                         cudaFuncAttributeMaxDynamicSharedMemorySize, SMEM_GEMM_BYTES);
    cudaFuncSetAttribute(gemm_split<false, true, false>,
                         cudaFuncAttributeMaxDynamicSharedMemorySize, SMEM_GEMM_BYTES);

    // -------- weight prep (tiny) --------
    transpose_split_k<<<dim3(DD / 32, HH1 / 32), dim3(32, 8)>>>(W1, HH1, DD, W1Thi, W1Tlo);

    // -------- forward pass (coalesced) --------
    fwd_w1<<<dim3(HH1 / 4,  BB / 4), 128>>>(x,  W1, b1,  c1, s1, nullptr, DD,  HH1);
    fwd_w1<<<dim3(HH2 / 4,  BB / 4), 128>>>(c1, W2, b2,  c2, s2, out_c2,  HH1, HH2);
    fwd_w0<<<dim3(HH1 / 32, BB / 4), 128>>>(c2, W2, b3,  c3, s3, HH2, HH1);
    fwd_w0<<<dim3(DD  / 32, BB / 4), 128>>>(c3, W1, b_r, out_rec, nullptr, HH1, DD);

    // -------- Jacobian chain (3-product bf16 HMMA, CTA 128x128, 2 CTA/SM) ----
    // A1: M1[b][d',e] = sum_h W1T[d',h]*s3[b,h]*W2[e,h]  -> bf16 pair
    gemm_split<true, false, false><<<dim3(HH2 / 128, DD / 128, BB), 128, SMEM_GEMM_BYTES>>>(
        W1Thi, W1Tlo, 0,
        W2, nullptr, nullptr, 0,
        s3, HH1,
        nullptr, 0,
        nullptr, M1hi, M1lo,
        (size_t)HH2, (size_t)DD * HH2);

    // A2: L[b][d,e] = (sum_h W1T[d,h]*s1[b,h]*W2[e,h]) * s2[b,e] -> bf16 pair
    gemm_split<true, false, true><<<dim3(HH2 / 128, DD / 128, BB), 128, SMEM_GEMM_BYTES>>>(
        W1Thi, W1Tlo, 0,
        W2, nullptr, nullptr, 0,
        s1, HH1,
        s2, HH2,
        nullptr, Lhi, Llo,
        (size_t)HH2, (size_t)DD * HH2);

    // C: Jac[b][d,d'] = sum_e L[b][d,e] * M1[b][d',e]  (K=256, both pairs)
    // flat offset(b,d,d') = d*(B*D) + b*D + d'  => ldc = B*D, strideC = D
    gemm_split<false, true, false><<<dim3(DD / 128, DD / 128, BB), 128, SMEM_GEMM_BYTES>>>(
        Lhi, Llo, (size_t)DD * HH2,
        nullptr, M1hi, M1lo, (size_t)DD * HH2,
        nullptr, HH2,
        nullptr, 0,
        out_jac, nullptr, nullptr,
        (size_t)BB * DD, (size_t)DD);
}

// round 13
// speedup vs baseline: 2.2470x; 1.0013x over previous
#include <cuda_runtime.h>
#include <cuda_bf16.h>
#include <cstdint>

#define BB   128
#define DD   1024
#define HH1  512
#define HH2  256

typedef unsigned int u32;
typedef unsigned long long u64;

// ---------------- scratch (device globals; no allocation allowed) ----------
__device__ float g_c1[BB * HH1];
__device__ float g_s1[BB * HH1];
__device__ float g_c2[BB * HH2];
__device__ float g_s2[BB * HH2];
__device__ float g_c3[BB * HH1];
__device__ float g_s3[BB * HH1];
__device__ float g_W1Tf[DD * HH1];                       // W1^T fp32 [1024,512]
__device__ float g_W2Tf[HH1 * HH2];                      // W2^T fp32 [512,256]
__device__ __nv_bfloat16 g_W1Thi[DD * HH1];              // W1^T hi  [1024,512]
__device__ __nv_bfloat16 g_W1Tlo[DD * HH1];              // W1^T lo
__device__ __nv_bfloat16 g_M1hi[(size_t)BB * DD * HH2];  // M1 pair [b][1024,256]
__device__ __nv_bfloat16 g_M1lo[(size_t)BB * DD * HH2];
__device__ __nv_bfloat16 g_Lhi[(size_t)BB * DD * HH2];   // L pair  [b][1024,256]
__device__ __nv_bfloat16 g_Llo[(size_t)BB * DD * HH2];

// ---------------- helpers ----------------------------------------------------
__device__ __forceinline__ u32 smem_u32(const void* p) {
    u32 a;
    asm("{ .reg .u64 t; cvta.to.shared.u64 t, %1; cvt.u32.u64 %0, t; }"
        : "=r"(a) : "l"(p));
    return a;
}

#define STS128(ad, v) \
    asm volatile("st.shared.v4.b32 [%0], {%1, %2, %3, %4};" \
                 :: "r"(ad), "r"((v).x), "r"((v).y), "r"((v).z), "r"((v).w) : "memory")

__device__ __forceinline__ void cpa16(u32 dst, const void* src) {
    asm volatile("cp.async.cg.shared.global [%0], [%1], 16;"
                 :: "r"(dst), "l"(src) : "memory");
}
#define CP_COMMIT() asm volatile("cp.async.commit_group;" ::: "memory")
#define CP_WAIT0()  asm volatile("cp.async.wait_group 0;" ::: "memory")

__device__ __forceinline__ void ldsm4(u32* r, u32 addr) {
    asm volatile("ldmatrix.sync.aligned.m8n8.x4.shared.b16 {%0,%1,%2,%3}, [%4];"
                 : "=r"(r[0]), "=r"(r[1]), "=r"(r[2]), "=r"(r[3]) : "r"(addr));
}

__device__ __forceinline__ void mma_bf16(float* c, const u32* a, const u32* b) {
    asm volatile("mma.sync.aligned.m16n8k16.row.col.f32.bf16.bf16.f32 "
                 "{%0,%1,%2,%3}, {%4,%5,%6,%7}, {%8,%9}, {%0,%1,%2,%3};"
                 : "+f"(c[0]), "+f"(c[1]), "+f"(c[2]), "+f"(c[3])
                 : "r"(a[0]), "r"(a[1]), "r"(a[2]), "r"(a[3]),
                   "r"(b[0]), "r"(b[1]));
}

// bf16 split: hi = rn(p) (bf16 bits), lo = p - hi (exact fp32)
__device__ __forceinline__ u32 split1(float p, float& lo) {
    u32 u = __float_as_uint(p);
    u32 r = (u + 0x7FFFu + ((u >> 16) & 1u)) & 0xFFFF0000u;
    lo = p - __uint_as_float(r);
    return r >> 16;
}
__device__ __forceinline__ u32 bf16rn(float p) {
    u32 u = __float_as_uint(p);
    return (u + 0x7FFFu + ((u >> 16) & 1u)) >> 16;
}

// ---------------- forward pass, row-major W (C = sig(A @ W^T + b)) -----------
// One warp per output n, lanes stride along K (fully coalesced), 4 samples.
// grid (N/4, B/4), block 128.
__global__ void fwd_w1(const float* __restrict__ A,
                       const float* __restrict__ W,
                       const float* __restrict__ bias,
                       float* __restrict__ c_out,
                       float* __restrict__ s_out,
                       float* __restrict__ extra_out,
                       int K, int N) {
    const int lane = threadIdx.x & 31;
    const int w    = threadIdx.x >> 5;
    const int n    = blockIdx.x * 4 + w;
    const int b0   = blockIdx.y * 4;
    const int K4   = K >> 2;
    const float4* W4 = (const float4*)(W + (size_t)n * K);
    const float4* X4 = (const float4*)(A + (size_t)b0 * K);
    float acc[4] = {0.f, 0.f, 0.f, 0.f};
    const int nit = K4 >> 5;            // 8 / 4 / 2
    #pragma unroll 4
    for (int ii = 0; ii < nit; ++ii) {
        const int i = ii * 32 + lane;
        float4 wv = W4[i];
        #pragma unroll
        for (int bi = 0; bi < 4; ++bi) {
            float4 xv = X4[(size_t)bi * K4 + i];
            acc[bi] += xv.x * wv.x + xv.y * wv.y + xv.z * wv.z + xv.w * wv.w;
        }
    }
    #pragma unroll
    for (int bi = 0; bi < 4; ++bi)
        #pragma unroll
        for (int o = 16; o; o >>= 1)
            acc[bi] += __shfl_xor_sync(0xFFFFFFFFu, acc[bi], o);
    if (lane == 0) {
        const float bv = bias[n];
        #pragma unroll
        for (int bi = 0; bi < 4; ++bi) {
            const float c = 1.0f / (1.0f + expf(-(acc[bi] + bv)));
            const size_t o = (size_t)(b0 + bi) * N + n;
            if (c_out)     c_out[o]     = c;
            if (s_out)     s_out[o]     = c * (1.0f - c);
            if (extra_out) extra_out[o] = c;
        }
    }
}

// ---------------- one-time transpose+split of W1 (bf16 pair + fp32) ----------
__global__ void transpose_split_k(const float* __restrict__ in, int R, int C,
                                  __nv_bfloat16* __restrict__ oh,
                                  __nv_bfloat16* __restrict__ ol,
                                  float* __restrict__ of) {
    __shared__ float t[32][33];
    const int c0 = blockIdx.x * 32, r0 = blockIdx.y * 32;
    const int tx = threadIdx.x, ty = threadIdx.y;
    #pragma unroll
    for (int i = 0; i < 32; i += 8)
        t[ty + i][tx] = in[(size_t)(r0 + ty + i) * C + c0 + tx];
    __syncthreads();
    #pragma unroll
    for (int i = 0; i < 32; i += 8) {
        float v = t[tx][ty + i];
        size_t o = (size_t)(c0 + ty + i) * R + r0 + tx;
        float lf; u32 h = split1(v, lf);
        ((unsigned short*)oh)[o] = (unsigned short)h;
        ((unsigned short*)ol)[o] = (unsigned short)bf16rn(lf);
        of[o] = v;
    }
}

// ---------------- one-time fp32 transpose (W2) -------------------------------
__global__ void transpose_f32(const float* __restrict__ in, int R, int C,
                              float* __restrict__ out) {
    __shared__ float t[32][33];
    const int c0 = blockIdx.x * 32, r0 = blockIdx.y * 32;
    const int tx = threadIdx.x, ty = threadIdx.y;
    #pragma unroll
    for (int i = 0; i < 32; i += 8)
        t[ty + i][tx] = in[(size_t)(r0 + ty + i) * C + c0 + tx];
    __syncthreads();
    #pragma unroll
    for (int i = 0; i < 32; i += 8)
        out[(size_t)(c0 + ty + i) * R + r0 + tx] = t[tx][ty + i];
}

// ---------------- HMMA split-bf16 batched GEMM, CTA 128x128, 2 CTA/SM --------
// out[b][m, n] = sum_k A[b][m,k] * (loader scale) * B[b][n,k]
// A: bf16 hi/lo pair (cp.async). B: fp32 + scale-split (B_PAIR=0, reg-staged)
// or bf16 pair (B_PAIR=1, cp.async). Warp tile 64x64, 4 warps (2M x 2N), BK=32.
#define ROWP        80
#define A_MAT       (128 * ROWP)            // 10240
#define OFF_AL      A_MAT
#define OFF_BH      (2 * A_MAT)
#define OFF_BL      (3 * A_MAT)
#define STAGE_BYTES (4 * A_MAT)             // 40960
#define SMEM_GEMM_BYTES (2 * STAGE_BYTES)   // 81920

template <bool OUT_PAIR, bool B_PAIR, bool EPI_SCALE>
__global__ void __launch_bounds__(128, 2)
gemm_split(const __nv_bfloat16* __restrict__ Ahi_g,
           const __nv_bfloat16* __restrict__ Alo_g, size_t strideA,
           const float* __restrict__ Bf_g,
           const __nv_bfloat16* __restrict__ Bhi_g,
           const __nv_bfloat16* __restrict__ Blo_g, size_t strideB,
           const float* __restrict__ sc_g, int K,
           const float* __restrict__ episc_g, int epiN,
           float* __restrict__ Cf,
           __nv_bfloat16* __restrict__ Chi, __nv_bfloat16* __restrict__ Clo,
           size_t ldc, size_t strideC) {
    extern __shared__ char smem[];
    const u32 sb  = smem_u32(smem);
    const int tid = threadIdx.x;
    const int wid = tid >> 5;
    const int lid = tid & 31;
    const int b   = blockIdx.z;
    const int n0  = blockIdx.x * 128;
    const int m0  = blockIdx.y * 128;

    const int m0w = (wid & 1) * 64;          // 2 warps in M
    const int n0w = (wid >> 1) * 64;         // 2 warps in N

    const __nv_bfloat16* Ahi_b = Ahi_g + (size_t)b * strideA;
    const __nv_bfloat16* Alo_b = Alo_g + (size_t)b * strideA;

    // loader: one tile row per thread
    const int r = tid;
    const size_t aRow = (size_t)(m0 + r) * K;
    const size_t bRow = (size_t)(n0 + r) * K;
    const u32 stoff = (u32)r * ROWP;

    // ldmatrix lane address bases
    const int l = lid;
    const u32 a_base = (u32)((m0w + (l & 7) + ((l >> 3) & 1) * 8) * ROWP
                             + ((l >> 4) & 1) * 16);
    const int mt = l >> 3;
    const u32 b_base = (u32)((n0w + ((mt >> 1) & 1) * 8 + (l & 7)) * ROWP
                             + (mt & 1) * 16);

    float acc[4][8][4];
    #pragma unroll
    for (int i = 0; i < 4; i++)
        #pragma unroll
        for (int j = 0; j < 8; j++)
            #pragma unroll
            for (int q = 0; q < 4; q++) acc[i][j][q] = 0.f;

    u32 hw[16], lw[16];                       // split staging (B_PAIR=0)

    auto issue_stage = [&](int sidx, int kt) {
        const u32 stg = sb + (u32)sidx * STAGE_BYTES + stoff;
        const char* ph = (const char*)(Ahi_b + aRow + kt);
        const char* pl = (const char*)(Alo_b + aRow + kt);
        #pragma unroll
        for (int j = 0; j < 4; ++j) cpa16(stg + j * 16, ph + j * 16);
        #pragma unroll
        for (int j = 0; j < 4; ++j) cpa16(stg + OFF_AL + j * 16, pl + j * 16);
        if (B_PAIR) {
            const char* qh = (const char*)(Bhi_g + (size_t)b * strideB + bRow + kt);
            const char* ql = (const char*)(Blo_g + (size_t)b * strideB + bRow + kt);
            #pragma unroll
            for (int j = 0; j < 4; ++j) cpa16(stg + OFF_BH + j * 16, qh + j * 16);
            #pragma unroll
            for (int j = 0; j < 4; ++j) cpa16(stg + OFF_BL + j * 16, ql + j * 16);
        }
        CP_COMMIT();
    };

    auto ldg_split = [&](int kt) {
        if (!B_PAIR) {
            const float4* pb = (const float4*)(Bf_g + (size_t)b * strideB + bRow + kt);
            const float4* ps = (const float4*)(sc_g + (size_t)b * K + kt);
            #pragma unroll
            for (int j = 0; j < 8; ++j) {
                float4 bv = pb[j];
                float4 sv = ps[j];
                float p0 = bv.x * sv.x, p1 = bv.y * sv.y;
                float p2 = bv.z * sv.z, p3 = bv.w * sv.w;
                float l0, l1, l2, l3;
                u32 h0 = split1(p0, l0), h1 = split1(p1, l1);
                u32 h2 = split1(p2, l2), h3 = split1(p3, l3);
                hw[j * 2 + 0] = h0 | (h1 << 16);
                hw[j * 2 + 1] = h2 | (h3 << 16);
                lw[j * 2 + 0] = bf16rn(l0) | (bf16rn(l1) << 16);
                lw[j * 2 + 1] = bf16rn(l2) | (bf16rn(l3) << 16);
            }
        }
    };

    const int niter = K >> 5;
    issue_stage(0, 0);
    ldg_split(0);

    for (int it = 0; it < niter; ++it) {
        const u32 stg = sb + (u32)(it & 1) * STAGE_BYTES;
        if (!B_PAIR) {
            const u32 d = stg + stoff;
            #pragma unroll
            for (int j = 0; j < 4; ++j) {
                uint4 vh = make_uint4(hw[4*j], hw[4*j+1], hw[4*j+2], hw[4*j+3]);
                uint4 vl = make_uint4(lw[4*j], lw[4*j+1], lw[4*j+2], lw[4*j+3]);
                STS128(d + OFF_BH + 16 * j, vh);
                STS128(d + OFF_BL + 16 * j, vl);
            }
        }
        CP_WAIT0();
        __syncthreads();
        if (it + 1 < niter) {
            issue_stage((it + 1) & 1, (it + 1) << 5);
            ldg_split((it + 1) << 5);
        }

        const u32 aH = stg + a_base;
        const u32 aL = stg + OFF_AL + a_base;
        const u32 bH = stg + OFF_BH + b_base;
        const u32 bL = stg + OFF_BL + b_base;

        #pragma unroll
        for (int ks = 0; ks < 2; ++ks) {
            u32 Ah[4][4], Al[4][4];
            #pragma unroll
            for (int mi = 0; mi < 4; ++mi) {
                ldsm4(Ah[mi], aH + mi * (16 * ROWP) + ks * 32);
                ldsm4(Al[mi], aL + mi * (16 * ROWP) + ks * 32);
            }
            #pragma unroll
            for (int jj = 0; jj < 4; ++jj) {
                u32 Bh[4], Bl[4];
                ldsm4(Bh, bH + jj * (16 * ROWP) + ks * 32);
                ldsm4(Bl, bL + jj * (16 * ROWP) + ks * 32);
                #pragma unroll
                for (int mi = 0; mi < 4; ++mi) {
                    mma_bf16(acc[mi][2 * jj],     Ah[mi], &Bh[0]);
                    mma_bf16(acc[mi][2 * jj + 1], Ah[mi], &Bh[2]);
                    mma_bf16(acc[mi][2 * jj],     Ah[mi], &Bl[0]);
                    mma_bf16(acc[mi][2 * jj + 1], Ah[mi], &Bl[2]);
                    mma_bf16(acc[mi][2 * jj],     Al[mi], &Bh[0]);
                    mma_bf16(acc[mi][2 * jj + 1], Al[mi], &Bh[2]);
                }
            }
        }
    }

    // ---- epilogue ----
    const int gid = lid >> 2;
    const int tig = lid & 3;
    #pragma unroll
    for (int mi = 0; mi < 4; ++mi) {
        #pragma unroll
        for (int nj = 0; nj < 8; ++nj) {
            const int row = m0 + m0w + 16 * mi + gid;
            const int col = n0 + n0w + 8 * nj + tig * 2;
            float a[4] = { acc[mi][nj][0], acc[mi][nj][1],
                           acc[mi][nj][2], acc[mi][nj][3] };
            if (EPI_SCALE) {
                const float* es = episc_g + (size_t)b * epiN + col;
                const float s0 = es[0], s1 = es[1];
                a[0] *= s0; a[1] *= s1; a[2] *= s0; a[3] *= s1;
            }
            const size_t o0 = (size_t)b * strideC + (size_t)row * ldc + col;
            const size_t o1 = o0 + 8 * ldc;
            if (OUT_PAIR) {
                float l0, l1, l2, l3;
                u32 h0 = split1(a[0], l0), h1 = split1(a[1], l1);
                u32 h2 = split1(a[2], l2), h3 = split1(a[3], l3);
                *(u32*)(Chi + o0) = h0 | (h1 << 16);
                *(u32*)(Clo + o0) = bf16rn(l0) | (bf16rn(l1) << 16);
                *(u32*)(Chi + o1) = h2 | (h3 << 16);
                *(u32*)(Clo + o1) = bf16rn(l2) | (bf16rn(l3) << 16);
            } else {
                *(float2*)(Cf + o0) = make_float2(a[0], a[1]);
                *(float2*)(Cf + o1) = make_float2(a[2], a[3]);
            }
        }
    }
}

// ---------------- launcher ---------------------------------------------------
extern "C" void kernel_launch(void* const* d_in, const int* in_sizes, int n_in,
                              void* d_out, int out_size) {
    const float* x   = (const float*)d_in[0];
    const float* W1  = (const float*)d_in[1];
    const float* b1  = (const float*)d_in[2];
    const float* W2  = (const float*)d_in[3];
    const float* b2  = (const float*)d_in[4];
    const float* b3  = (const float*)d_in[5];
    const float* b_r = (const float*)d_in[6];

    float* out     = (float*)d_out;
    float* out_rec = out;                           // [128,1024]
    float* out_c2  = out + (size_t)BB * DD;         // [128,256]
    float* out_jac = out_c2 + (size_t)BB * HH2;     // [D, B, D] flat

    float *c1, *s1, *c2, *s2, *c3, *s3, *W1Tf, *W2Tf;
    __nv_bfloat16 *W1Thi, *W1Tlo, *M1hi, *M1lo, *Lhi, *Llo;
    cudaGetSymbolAddress((void**)&c1, g_c1);
    cudaGetSymbolAddress((void**)&s1, g_s1);
    cudaGetSymbolAddress((void**)&c2, g_c2);
    cudaGetSymbolAddress((void**)&s2, g_s2);
    cudaGetSymbolAddress((void**)&c3, g_c3);
    cudaGetSymbolAddress((void**)&s3, g_s3);
    cudaGetSymbolAddress((void**)&W1Tf, g_W1Tf);
    cudaGetSymbolAddress((void**)&W2Tf, g_W2Tf);
    cudaGetSymbolAddress((void**)&W1Thi, g_W1Thi);
    cudaGetSymbolAddress((void**)&W1Tlo, g_W1Tlo);
    cudaGetSymbolAddress((void**)&M1hi, g_M1hi);
    cudaGetSymbolAddress((void**)&M1lo, g_M1lo);
    cudaGetSymbolAddress((void**)&Lhi, g_Lhi);
    cudaGetSymbolAddress((void**)&Llo, g_Llo);

    cudaFuncSetAttribute(gemm_split<true, false, false>,
                         cudaFuncAttributeMaxDynamicSharedMemorySize, SMEM_GEMM_BYTES);
    cudaFuncSetAttribute(gemm_split<true, false, true>,
                         cudaFuncAttributeMaxDynamicSharedMemorySize, SMEM_GEMM_BYTES);
    cudaFuncSetAttribute(gemm_split<false, true, false>,
                         cudaFuncAttributeMaxDynamicSharedMemorySize, SMEM_GEMM_BYTES);

    // -------- weight prep (tiny) --------
    transpose_split_k<<<dim3(DD / 32, HH1 / 32), dim3(32, 8)>>>(W1, HH1, DD,
                                                                W1Thi, W1Tlo, W1Tf);
    transpose_f32<<<dim3(HH1 / 32, HH2 / 32), dim3(32, 8)>>>(W2, HH2, HH1, W2Tf);

    // -------- forward pass (all layers coalesced, warp-per-output) --------
    fwd_w1<<<dim3(HH1 / 4, BB / 4), 128>>>(x,  W1,   b1,  c1, s1, nullptr, DD,  HH1);
    fwd_w1<<<dim3(HH2 / 4, BB / 4), 128>>>(c1, W2,   b2,  c2, s2, out_c2,  HH1, HH2);
    fwd_w1<<<dim3(HH1 / 4, BB / 4), 128>>>(c2, W2Tf, b3,  c3, s3, nullptr, HH2, HH1);
    fwd_w1<<<dim3(DD  / 4, BB / 4), 128>>>(c3, W1Tf, b_r, out_rec, nullptr, nullptr, HH1, DD);

    // -------- Jacobian chain (3-product bf16 HMMA, CTA 128x128, 2 CTA/SM) ----
    // A1: M1[b][d',e] = sum_h W1T[d',h]*s3[b,h]*W2[e,h]  -> bf16 pair
    gemm_split<true, false, false><<<dim3(HH2 / 128, DD / 128, BB), 128, SMEM_GEMM_BYTES>>>(
        W1Thi, W1Tlo, 0,
        W2, nullptr, nullptr, 0,
        s3, HH1,
        nullptr, 0,
        nullptr, M1hi, M1lo,
        (size_t)HH2, (size_t)DD * HH2);

    // A2: L[b][d,e] = (sum_h W1T[d,h]*s1[b,h]*W2[e,h]) * s2[b,e] -> bf16 pair
    gemm_split<true, false, true><<<dim3(HH2 / 128, DD / 128, BB), 128, SMEM_GEMM_BYTES>>>(
        W1Thi, W1Tlo, 0,
        W2, nullptr, nullptr, 0,
        s1, HH1,
        s2, HH2,
        nullptr, Lhi, Llo,
        (size_t)HH2, (size_t)DD * HH2);

    // C: Jac[b][d,d'] = sum_e L[b][d,e] * M1[b][d',e]  (K=256, both pairs)
    // flat offset(b,d,d') = d*(B*D) + b*D + d'  => ldc = B*D, strideC = D
    gemm_split<false, true, false><<<dim3(DD / 128, DD / 128, BB), 128, SMEM_GEMM_BYTES>>>(
        Lhi, Llo, (size_t)DD * HH2,
        nullptr, M1hi, M1lo, (size_t)DD * HH2,
        nullptr, HH2,
        nullptr, 0,
        out_jac, nullptr, nullptr,
        (size_t)BB * DD, (size_t)DD);
}

// round 14
// speedup vs baseline: 2.2540x; 1.0031x over previous
#include <cuda_runtime.h>
#include <cuda_bf16.h>
#include <cstdint>

#define BB   128
#define DD   1024
#define HH1  512
#define HH2  256

typedef unsigned int u32;
typedef unsigned long long u64;

// ---------------- scratch (device globals; no allocation allowed) ----------
__device__ float g_c1[BB * HH1];
__device__ float g_s1[BB * HH1];
__device__ float g_c2[BB * HH2];
__device__ float g_s2[BB * HH2];
__device__ float g_c3[BB * HH1];
__device__ float g_s3[BB * HH1];
__device__ float g_W1Tf[DD * HH1];                       // W1^T fp32 [1024,512]
__device__ float g_W2Tf[HH1 * HH2];                      // W2^T fp32 [512,256]
__device__ __nv_bfloat16 g_W1Thi[DD * HH1];              // W1^T hi  [1024,512]
__device__ __nv_bfloat16 g_W1Tlo[DD * HH1];              // W1^T lo
__device__ __nv_bfloat16 g_M1hi[(size_t)BB * DD * HH2];  // M1 pair [b][1024,256]
__device__ __nv_bfloat16 g_M1lo[(size_t)BB * DD * HH2];
__device__ __nv_bfloat16 g_Lhi[(size_t)BB * DD * HH2];   // L pair  [b][1024,256]
__device__ __nv_bfloat16 g_Llo[(size_t)BB * DD * HH2];

// ---------------- helpers ----------------------------------------------------
__device__ __forceinline__ u32 smem_u32(const void* p) {
    u32 a;
    asm("{ .reg .u64 t; cvta.to.shared.u64 t, %1; cvt.u32.u64 %0, t; }"
        : "=r"(a) : "l"(p));
    return a;
}

#define STS128(ad, v) \
    asm volatile("st.shared.v4.b32 [%0], {%1, %2, %3, %4};" \
                 :: "r"(ad), "r"((v).x), "r"((v).y), "r"((v).z), "r"((v).w) : "memory")

__device__ __forceinline__ void cpa16(u32 dst, const void* src) {
    asm volatile("cp.async.cg.shared.global [%0], [%1], 16;"
                 :: "r"(dst), "l"(src) : "memory");
}
#define CP_COMMIT() asm volatile("cp.async.commit_group;" ::: "memory")
#define CP_WAIT0()  asm volatile("cp.async.wait_group 0;" ::: "memory")

__device__ __forceinline__ void ldsm4(u32* r, u32 addr) {
    asm volatile("ldmatrix.sync.aligned.m8n8.x4.shared.b16 {%0,%1,%2,%3}, [%4];"
                 : "=r"(r[0]), "=r"(r[1]), "=r"(r[2]), "=r"(r[3]) : "r"(addr));
}

__device__ __forceinline__ void mma_bf16(float* c, const u32* a, const u32* b) {
    asm volatile("mma.sync.aligned.m16n8k16.row.col.f32.bf16.bf16.f32 "
                 "{%0,%1,%2,%3}, {%4,%5,%6,%7}, {%8,%9}, {%0,%1,%2,%3};"
                 : "+f"(c[0]), "+f"(c[1]), "+f"(c[2]), "+f"(c[3])
                 : "r"(a[0]), "r"(a[1]), "r"(a[2]), "r"(a[3]),
                   "r"(b[0]), "r"(b[1]));
}

// bf16 split: hi = rn(p) (bf16 bits), lo = p - hi (exact fp32)
__device__ __forceinline__ u32 split1(float p, float& lo) {
    u32 u = __float_as_uint(p);
    u32 r = (u + 0x7FFFu + ((u >> 16) & 1u)) & 0xFFFF0000u;
    lo = p - __uint_as_float(r);
    return r >> 16;
}
__device__ __forceinline__ u32 bf16rn(float p) {
    u32 u = __float_as_uint(p);
    return (u + 0x7FFFu + ((u >> 16) & 1u)) >> 16;
}

// ---------------- forward pass, row-major W (C = sig(A @ W^T + b)) -----------
// One warp per output n, lanes stride along K (fully coalesced), 8 samples
// per block (halves W L2 traffic). grid (N/4, B/8), block 128.
__global__ void fwd_w1(const float* __restrict__ A,
                       const float* __restrict__ W,
                       const float* __restrict__ bias,
                       float* __restrict__ c_out,
                       float* __restrict__ s_out,
                       float* __restrict__ extra_out,
                       int K, int N) {
    const int lane = threadIdx.x & 31;
    const int w    = threadIdx.x >> 5;
    const int n    = blockIdx.x * 4 + w;
    const int b0   = blockIdx.y * 8;
    const int K4   = K >> 2;
    const float4* W4 = (const float4*)(W + (size_t)n * K);
    const float4* X4 = (const float4*)(A + (size_t)b0 * K);
    float acc[8] = {0.f, 0.f, 0.f, 0.f, 0.f, 0.f, 0.f, 0.f};
    const int nit = K4 >> 5;            // 8 / 4 / 2
    #pragma unroll 4
    for (int ii = 0; ii < nit; ++ii) {
        const int i = ii * 32 + lane;
        float4 wv = W4[i];
        #pragma unroll
        for (int bi = 0; bi < 8; ++bi) {
            float4 xv = X4[(size_t)bi * K4 + i];
            acc[bi] += xv.x * wv.x + xv.y * wv.y + xv.z * wv.z + xv.w * wv.w;
        }
    }
    #pragma unroll
    for (int bi = 0; bi < 8; ++bi)
        #pragma unroll
        for (int o = 16; o; o >>= 1)
            acc[bi] += __shfl_xor_sync(0xFFFFFFFFu, acc[bi], o);
    if (lane == 0) {
        const float bv = bias[n];
        #pragma unroll
        for (int bi = 0; bi < 8; ++bi) {
            const float c = 1.0f / (1.0f + expf(-(acc[bi] + bv)));
            const size_t o = (size_t)(b0 + bi) * N + n;
            if (c_out)     c_out[o]     = c;
            if (s_out)     s_out[o]     = c * (1.0f - c);
            if (extra_out) extra_out[o] = c;
        }
    }
}

// ---------------- one-time transpose+split of W1 (bf16 pair + fp32) ----------
__global__ void transpose_split_k(const float* __restrict__ in, int R, int C,
                                  __nv_bfloat16* __restrict__ oh,
                                  __nv_bfloat16* __restrict__ ol,
                                  float* __restrict__ of) {
    __shared__ float t[32][33];
    const int c0 = blockIdx.x * 32, r0 = blockIdx.y * 32;
    const int tx = threadIdx.x, ty = threadIdx.y;
    #pragma unroll
    for (int i = 0; i < 32; i += 8)
        t[ty + i][tx] = in[(size_t)(r0 + ty + i) * C + c0 + tx];
    __syncthreads();
    #pragma unroll
    for (int i = 0; i < 32; i += 8) {
        float v = t[tx][ty + i];
        size_t o = (size_t)(c0 + ty + i) * R + r0 + tx;
        float lf; u32 h = split1(v, lf);
        ((unsigned short*)oh)[o] = (unsigned short)h;
        ((unsigned short*)ol)[o] = (unsigned short)bf16rn(lf);
        of[o] = v;
    }
}

// ---------------- one-time fp32 transpose (W2) -------------------------------
__global__ void transpose_f32(const float* __restrict__ in, int R, int C,
                              float* __restrict__ out) {
    __shared__ float t[32][33];
    const int c0 = blockIdx.x * 32, r0 = blockIdx.y * 32;
    const int tx = threadIdx.x, ty = threadIdx.y;
    #pragma unroll
    for (int i = 0; i < 32; i += 8)
        t[ty + i][tx] = in[(size_t)(r0 + ty + i) * C + c0 + tx];
    __syncthreads();
    #pragma unroll
    for (int i = 0; i < 32; i += 8)
        out[(size_t)(c0 + ty + i) * R + r0 + tx] = t[tx][ty + i];
}

// ---------------- HMMA split-bf16 batched GEMM, CTA 128x128, 2 CTA/SM --------
// out[b][m, n] = sum_k A[b][m,k] * (loader scale) * B[b][n,k]
// A: bf16 hi/lo pair (cp.async). B: fp32 + scale-split (B_PAIR=0, reg-staged)
// or bf16 pair (B_PAIR=1, cp.async). Warp tile 64x64, 4 warps (2M x 2N), BK=32.
#define ROWP        80
#define A_MAT       (128 * ROWP)            // 10240
#define OFF_AL      A_MAT
#define OFF_BH      (2 * A_MAT)
#define OFF_BL      (3 * A_MAT)
#define STAGE_BYTES (4 * A_MAT)             // 40960
#define SMEM_GEMM_BYTES (2 * STAGE_BYTES)   // 81920

template <bool OUT_PAIR, bool B_PAIR, bool EPI_SCALE>
__global__ void __launch_bounds__(128, 2)
gemm_split(const __nv_bfloat16* __restrict__ Ahi_g,
           const __nv_bfloat16* __restrict__ Alo_g, size_t strideA,
           const float* __restrict__ Bf_g,
           const __nv_bfloat16* __restrict__ Bhi_g,
           const __nv_bfloat16* __restrict__ Blo_g, size_t strideB,
           const float* __restrict__ sc_g, int K,
           const float* __restrict__ episc_g, int epiN,
           float* __restrict__ Cf,
           __nv_bfloat16* __restrict__ Chi, __nv_bfloat16* __restrict__ Clo,
           size_t ldc, size_t strideC) {
    extern __shared__ char smem[];
    const u32 sb  = smem_u32(smem);
    const int tid = threadIdx.x;
    const int wid = tid >> 5;
    const int lid = tid & 31;
    const int b   = blockIdx.z;
    const int n0  = blockIdx.x * 128;
    const int m0  = blockIdx.y * 128;

    const int m0w = (wid & 1) * 64;          // 2 warps in M
    const int n0w = (wid >> 1) * 64;         // 2 warps in N

    const __nv_bfloat16* Ahi_b = Ahi_g + (size_t)b * strideA;
    const __nv_bfloat16* Alo_b = Alo_g + (size_t)b * strideA;

    // loader: one tile row per thread
    const int r = tid;
    const size_t aRow = (size_t)(m0 + r) * K;
    const size_t bRow = (size_t)(n0 + r) * K;
    const u32 stoff = (u32)r * ROWP;

    // ldmatrix lane address bases
    const int l = lid;
    const u32 a_base = (u32)((m0w + (l & 7) + ((l >> 3) & 1) * 8) * ROWP
                             + ((l >> 4) & 1) * 16);
    const int mt = l >> 3;
    const u32 b_base = (u32)((n0w + ((mt >> 1) & 1) * 8 + (l & 7)) * ROWP
                             + (mt & 1) * 16);

    float acc[4][8][4];
    #pragma unroll
    for (int i = 0; i < 4; i++)
        #pragma unroll
        for (int j = 0; j < 8; j++)
            #pragma unroll
            for (int q = 0; q < 4; q++) acc[i][j][q] = 0.f;

    u32 hw[16], lw[16];                       // split staging (B_PAIR=0)

    auto issue_stage = [&](int sidx, int kt) {
        const u32 stg = sb + (u32)sidx * STAGE_BYTES + stoff;
        const char* ph = (const char*)(Ahi_b + aRow + kt);
        const char* pl = (const char*)(Alo_b + aRow + kt);
        #pragma unroll
        for (int j = 0; j < 4; ++j) cpa16(stg + j * 16, ph + j * 16);
        #pragma unroll
        for (int j = 0; j < 4; ++j) cpa16(stg + OFF_AL + j * 16, pl + j * 16);
        if (B_PAIR) {
            const char* qh = (const char*)(Bhi_g + (size_t)b * strideB + bRow + kt);
            const char* ql = (const char*)(Blo_g + (size_t)b * strideB + bRow + kt);
            #pragma unroll
            for (int j = 0; j < 4; ++j) cpa16(stg + OFF_BH + j * 16, qh + j * 16);
            #pragma unroll
            for (int j = 0; j < 4; ++j) cpa16(stg + OFF_BL + j * 16, ql + j * 16);
        }
        CP_COMMIT();
    };

    auto ldg_split = [&](int kt) {
        if (!B_PAIR) {
            const float4* pb = (const float4*)(Bf_g + (size_t)b * strideB + bRow + kt);
            const float4* ps = (const float4*)(sc_g + (size_t)b * K + kt);
            #pragma unroll
            for (int j = 0; j < 8; ++j) {
                float4 bv = pb[j];
                float4 sv = ps[j];
                float p0 = bv.x * sv.x, p1 = bv.y * sv.y;
                float p2 = bv.z * sv.z, p3 = bv.w * sv.w;
                float l0, l1, l2, l3;
                u32 h0 = split1(p0, l0), h1 = split1(p1, l1);
                u32 h2 = split1(p2, l2), h3 = split1(p3, l3);
                hw[j * 2 + 0] = h0 | (h1 << 16);
                hw[j * 2 + 1] = h2 | (h3 << 16);
                lw[j * 2 + 0] = bf16rn(l0) | (bf16rn(l1) << 16);
                lw[j * 2 + 1] = bf16rn(l2) | (bf16rn(l3) << 16);
            }
        }
    };

    const int niter = K >> 5;
    issue_stage(0, 0);
    ldg_split(0);

    for (int it = 0; it < niter; ++it) {
        const u32 stg = sb + (u32)(it & 1) * STAGE_BYTES;
        if (!B_PAIR) {
            const u32 d = stg + stoff;
            #pragma unroll
            for (int j = 0; j < 4; ++j) {
                uint4 vh = make_uint4(hw[4*j], hw[4*j+1], hw[4*j+2], hw[4*j+3]);
                uint4 vl = make_uint4(lw[4*j], lw[4*j+1], lw[4*j+2], lw[4*j+3]);
                STS128(d + OFF_BH + 16 * j, vh);
                STS128(d + OFF_BL + 16 * j, vl);
            }
        }
        CP_WAIT0();
        __syncthreads();
        if (it + 1 < niter) {
            issue_stage((it + 1) & 1, (it + 1) << 5);
            ldg_split((it + 1) << 5);
        }

        const u32 aH = stg + a_base;
        const u32 aL = stg + OFF_AL + a_base;
        const u32 bH = stg + OFF_BH + b_base;
        const u32 bL = stg + OFF_BL + b_base;

        #pragma unroll
        for (int ks = 0; ks < 2; ++ks) {
            u32 Ah[4][4], Al[4][4];
            #pragma unroll
            for (int mi = 0; mi < 4; ++mi) {
                ldsm4(Ah[mi], aH + mi * (16 * ROWP) + ks * 32);
                ldsm4(Al[mi], aL + mi * (16 * ROWP) + ks * 32);
            }
            #pragma unroll
            for (int jj = 0; jj < 4; ++jj) {
                u32 Bh[4], Bl[4];
                ldsm4(Bh, bH + jj * (16 * ROWP) + ks * 32);
                ldsm4(Bl, bL + jj * (16 * ROWP) + ks * 32);
                #pragma unroll
                for (int mi = 0; mi < 4; ++mi) {
                    mma_bf16(acc[mi][2 * jj],     Ah[mi], &Bh[0]);
                    mma_bf16(acc[mi][2 * jj + 1], Ah[mi], &Bh[2]);
                    mma_bf16(acc[mi][2 * jj],     Ah[mi], &Bl[0]);
                    mma_bf16(acc[mi][2 * jj + 1], Ah[mi], &Bl[2]);
                    mma_bf16(acc[mi][2 * jj],     Al[mi], &Bh[0]);
                    mma_bf16(acc[mi][2 * jj + 1], Al[mi], &Bh[2]);
                }
            }
        }
    }

    // ---- epilogue ----
    const int gid = lid >> 2;
    const int tig = lid & 3;
    #pragma unroll
    for (int mi = 0; mi < 4; ++mi) {
        #pragma unroll
        for (int nj = 0; nj < 8; ++nj) {
            const int row = m0 + m0w + 16 * mi + gid;
            const int col = n0 + n0w + 8 * nj + tig * 2;
            float a[4] = { acc[mi][nj][0], acc[mi][nj][1],
                           acc[mi][nj][2], acc[mi][nj][3] };
            if (EPI_SCALE) {
                const float* es = episc_g + (size_t)b * epiN + col;
                const float s0 = es[0], s1 = es[1];
                a[0] *= s0; a[1] *= s1; a[2] *= s0; a[3] *= s1;
            }
            const size_t o0 = (size_t)b * strideC + (size_t)row * ldc + col;
            const size_t o1 = o0 + 8 * ldc;
            if (OUT_PAIR) {
                float l0, l1, l2, l3;
                u32 h0 = split1(a[0], l0), h1 = split1(a[1], l1);
                u32 h2 = split1(a[2], l2), h3 = split1(a[3], l3);
                *(u32*)(Chi + o0) = h0 | (h1 << 16);
                *(u32*)(Clo + o0) = bf16rn(l0) | (bf16rn(l1) << 16);
                *(u32*)(Chi + o1) = h2 | (h3 << 16);
                *(u32*)(Clo + o1) = bf16rn(l2) | (bf16rn(l3) << 16);
            } else {
                *(float2*)(Cf + o0) = make_float2(a[0], a[1]);
                *(float2*)(Cf + o1) = make_float2(a[2], a[3]);
            }
        }
    }
}

// ---------------- launcher ---------------------------------------------------
extern "C" void kernel_launch(void* const* d_in, const int* in_sizes, int n_in,
                              void* d_out, int out_size) {
    const float* x   = (const float*)d_in[0];
    const float* W1  = (const float*)d_in[1];
    const float* b1  = (const float*)d_in[2];
    const float* W2  = (const float*)d_in[3];
    const float* b2  = (const float*)d_in[4];
    const float* b3  = (const float*)d_in[5];
    const float* b_r = (const float*)d_in[6];

    float* out     = (float*)d_out;
    float* out_rec = out;                           // [128,1024]
    float* out_c2  = out + (size_t)BB * DD;         // [128,256]
    float* out_jac = out_c2 + (size_t)BB * HH2;     // [D, B, D] flat

    float *c1, *s1, *c2, *s2, *c3, *s3, *W1Tf, *W2Tf;
    __nv_bfloat16 *W1Thi, *W1Tlo, *M1hi, *M1lo, *Lhi, *Llo;
    cudaGetSymbolAddress((void**)&c1, g_c1);
    cudaGetSymbolAddress((void**)&s1, g_s1);
    cudaGetSymbolAddress((void**)&c2, g_c2);
    cudaGetSymbolAddress((void**)&s2, g_s2);
    cudaGetSymbolAddress((void**)&c3, g_c3);
    cudaGetSymbolAddress((void**)&s3, g_s3);
    cudaGetSymbolAddress((void**)&W1Tf, g_W1Tf);
    cudaGetSymbolAddress((void**)&W2Tf, g_W2Tf);
    cudaGetSymbolAddress((void**)&W1Thi, g_W1Thi);
    cudaGetSymbolAddress((void**)&W1Tlo, g_W1Tlo);
    cudaGetSymbolAddress((void**)&M1hi, g_M1hi);
    cudaGetSymbolAddress((void**)&M1lo, g_M1lo);
    cudaGetSymbolAddress((void**)&Lhi, g_Lhi);
    cudaGetSymbolAddress((void**)&Llo, g_Llo);

    cudaFuncSetAttribute(gemm_split<true, false, false>,
                         cudaFuncAttributeMaxDynamicSharedMemorySize, SMEM_GEMM_BYTES);
    cudaFuncSetAttribute(gemm_split<true, false, true>,
                         cudaFuncAttributeMaxDynamicSharedMemorySize, SMEM_GEMM_BYTES);
    cudaFuncSetAttribute(gemm_split<false, true, false>,
                         cudaFuncAttributeMaxDynamicSharedMemorySize, SMEM_GEMM_BYTES);

    // -------- weight prep (tiny) --------
    transpose_split_k<<<dim3(DD / 32, HH1 / 32), dim3(32, 8)>>>(W1, HH1, DD,
                                                                W1Thi, W1Tlo, W1Tf);
    transpose_f32<<<dim3(HH1 / 32, HH2 / 32), dim3(32, 8)>>>(W2, HH2, HH1, W2Tf);

    // -------- forward pass (all layers coalesced, warp-per-output, 8 b/blk) --
    fwd_w1<<<dim3(HH1 / 4, BB / 8), 128>>>(x,  W1,   b1,  c1, s1, nullptr, DD,  HH1);
    fwd_w1<<<dim3(HH2 / 4, BB / 8), 128>>>(c1, W2,   b2,  c2, s2, out_c2,  HH1, HH2);
    fwd_w1<<<dim3(HH1 / 4, BB / 8), 128>>>(c2, W2Tf, b3,  c3, s3, nullptr, HH2, HH1);
    fwd_w1<<<dim3(DD  / 4, BB / 8), 128>>>(c3, W1Tf, b_r, out_rec, nullptr, nullptr, HH1, DD);

    // -------- Jacobian chain (3-product bf16 HMMA, CTA 128x128, 2 CTA/SM) ----
    // A1: M1[b][d',e] = sum_h W1T[d',h]*s3[b,h]*W2[e,h]  -> bf16 pair
    gemm_split<true, false, false><<<dim3(HH2 / 128, DD / 128, BB), 128, SMEM_GEMM_BYTES>>>(
        W1Thi, W1Tlo, 0,
        W2, nullptr, nullptr, 0,
        s3, HH1,
        nullptr, 0,
        nullptr, M1hi, M1lo,
        (size_t)HH2, (size_t)DD * HH2);

    // A2: L[b][d,e] = (sum_h W1T[d,h]*s1[b,h]*W2[e,h]) * s2[b,e] -> bf16 pair
    gemm_split<true, false, true><<<dim3(HH2 / 128, DD / 128, BB), 128, SMEM_GEMM_BYTES>>>(
        W1Thi, W1Tlo, 0,
        W2, nullptr, nullptr, 0,
        s1, HH1,
        s2, HH2,
        nullptr, Lhi, Llo,
        (size_t)HH2, (size_t)DD * HH2);

    // C: Jac[b][d,d'] = sum_e L[b][d,e] * M1[b][d',e]  (K=256, both pairs)
    // flat offset(b,d,d') = d*(B*D) + b*D + d'  => ldc = B*D, strideC = D
    gemm_split<false, true, false><<<dim3(DD / 128, DD / 128, BB), 128, SMEM_GEMM_BYTES>>>(
        Lhi, Llo, (size_t)DD * HH2,
        nullptr, M1hi, M1lo, (size_t)DD * HH2,
        nullptr, HH2,
        nullptr, 0,
        out_jac, nullptr, nullptr,
        (size_t)BB * DD, (size_t)DD);
}